// round 5
// baseline (speedup 1.0000x reference)
#include <cuda_runtime.h>
#include <cstdint>

#define NN 50000
#define NE 800000
#define HID 128

// ---------------- scratch (static device arrays; no allocation) ----------------
__device__ float g_img_f[(size_t)NN * HID];
__device__ float g_txt_f[(size_t)NN * HID];
__device__ float g_h1   [(size_t)NN * HID];
__device__ float g_h2   [(size_t)NN * HID];
__device__ float g_img_v[(size_t)NN * HID];
__device__ float g_txt_v[(size_t)NN * HID];
__device__ float g_hbuf [(size_t)NN * HID];
__device__ float g_z    [(size_t)NN * HID];
__device__ float g_esrc [NN];
__device__ float g_edst [NN];
__device__ unsigned g_emax[NN];
__device__ float g_denom[NN];
__device__ float g_e    [NE];

// ordered encoding of float for atomicMax on unsigned
__device__ __forceinline__ unsigned fenc(float f) {
    unsigned u = __float_as_uint(f);
    return (u & 0x80000000u) ? ~u : (u | 0x80000000u);
}
__device__ __forceinline__ float fdec(unsigned u) {
    return (u & 0x80000000u) ? __uint_as_float(u & 0x7FFFFFFFu)
                             : __uint_as_float(~u);
}
// fenc(-inf) == 0x007FFFFF
#define ENC_NEG_INF 0x007FFFFFu

// ---------------------------------------------------------------------------
// SGEMM: C[M x 128] = act(A[M x K] @ B[K x 128] (+bias)), K % 16 == 0
// block tile 128x128, k-tile 16, 256 threads, 8x8 per-thread microtile
// ---------------------------------------------------------------------------
template<bool BIAS, bool RELU>
__global__ __launch_bounds__(256)
void gemm_dense(const float* __restrict__ A, const float* __restrict__ B,
                const float* __restrict__ bias, float* __restrict__ C,
                int M, int K)
{
    __shared__ float As[16][128];
    __shared__ float Bs[16][128];
    const int tid = threadIdx.x;
    const int m0  = blockIdx.x * 128;
    const int ty  = tid >> 4, tx = tid & 15;
    const int ar  = tid >> 2, ac = (tid & 3) << 2;
    const int br  = tid >> 5, bc = (tid & 31) << 2;

    float acc[8][8];
#pragma unroll
    for (int i = 0; i < 8; i++)
#pragma unroll
        for (int j = 0; j < 8; j++) acc[i][j] = 0.f;

    for (int k0 = 0; k0 < K; k0 += 16) {
#pragma unroll
        for (int hh = 0; hh < 2; hh++) {
            int row = m0 + ar + hh * 64;
            float4 v = make_float4(0.f, 0.f, 0.f, 0.f);
            if (row < M) v = *(const float4*)(A + (size_t)row * K + (k0 + ac));
            As[ac + 0][ar + hh * 64] = v.x;
            As[ac + 1][ar + hh * 64] = v.y;
            As[ac + 2][ar + hh * 64] = v.z;
            As[ac + 3][ar + hh * 64] = v.w;
        }
#pragma unroll
        for (int hh = 0; hh < 2; hh++) {
            int kk = br + hh * 8;
            *(float4*)&Bs[kk][bc] = *(const float4*)(B + (size_t)(k0 + kk) * HID + bc);
        }
        __syncthreads();
#pragma unroll
        for (int k = 0; k < 16; k++) {
            float a[8], b[8];
            *(float4*)&a[0] = *(const float4*)&As[k][ty * 8];
            *(float4*)&a[4] = *(const float4*)&As[k][ty * 8 + 4];
            *(float4*)&b[0] = *(const float4*)&Bs[k][tx * 8];
            *(float4*)&b[4] = *(const float4*)&Bs[k][tx * 8 + 4];
#pragma unroll
            for (int i = 0; i < 8; i++)
#pragma unroll
                for (int j = 0; j < 8; j++) acc[i][j] += a[i] * b[j];
        }
        __syncthreads();
    }
#pragma unroll
    for (int i = 0; i < 8; i++) {
        int row = m0 + ty * 8 + i;
        if (row >= M) continue;
#pragma unroll
        for (int j = 0; j < 8; j++) {
            int col = tx * 8 + j;
            float v = acc[i][j];
            if (BIAS) v += bias[col];
            if (RELU) v = fmaxf(v, 0.f);
            C[(size_t)row * HID + col] = v;
        }
    }
}

// ---------------------------------------------------------------------------
// Concat SGEMM: A row r = [ P[gidx?gidx[r]:r] (128) | Q[r] (128) ], K = 256
// MODE 0: C = relu(A@B + bias)                        (gate MLP layer 1)
// MODE 1: gate = A@B + bias; C = gate*P + (1-gate)*Q  (comb combine, no gather)
// ---------------------------------------------------------------------------
template<int MODE>
__global__ __launch_bounds__(256)
void gemm_cat(const float* __restrict__ P, const float* __restrict__ Q,
              const int* __restrict__ gidx,
              const float* __restrict__ B, const float* __restrict__ bias,
              float* __restrict__ C, int M)
{
    __shared__ float As[16][128];
    __shared__ float Bs[16][128];
    const int tid = threadIdx.x;
    const int m0  = blockIdx.x * 128;
    const int ty  = tid >> 4, tx = tid & 15;
    const int ar  = tid >> 2, ac = (tid & 3) << 2;
    const int br  = tid >> 5, bc = (tid & 31) << 2;

    float acc[8][8];
#pragma unroll
    for (int i = 0; i < 8; i++)
#pragma unroll
        for (int j = 0; j < 8; j++) acc[i][j] = 0.f;

    for (int k0 = 0; k0 < 256; k0 += 16) {
        const float* S = (k0 < 128) ? P : Q;
        const int cbase = (k0 < 128) ? k0 : (k0 - 128);
#pragma unroll
        for (int hh = 0; hh < 2; hh++) {
            int row = m0 + ar + hh * 64;
            float4 v = make_float4(0.f, 0.f, 0.f, 0.f);
            if (row < M) {
                int rr = row;
                if (MODE == 0 && k0 < 128) rr = gidx[row];
                v = *(const float4*)(S + (size_t)rr * HID + cbase + ac);
            }
            As[ac + 0][ar + hh * 64] = v.x;
            As[ac + 1][ar + hh * 64] = v.y;
            As[ac + 2][ar + hh * 64] = v.z;
            As[ac + 3][ar + hh * 64] = v.w;
        }
#pragma unroll
        for (int hh = 0; hh < 2; hh++) {
            int kk = br + hh * 8;
            *(float4*)&Bs[kk][bc] = *(const float4*)(B + (size_t)(k0 + kk) * HID + bc);
        }
        __syncthreads();
#pragma unroll
        for (int k = 0; k < 16; k++) {
            float a[8], b[8];
            *(float4*)&a[0] = *(const float4*)&As[k][ty * 8];
            *(float4*)&a[4] = *(const float4*)&As[k][ty * 8 + 4];
            *(float4*)&b[0] = *(const float4*)&Bs[k][tx * 8];
            *(float4*)&b[4] = *(const float4*)&Bs[k][tx * 8 + 4];
#pragma unroll
            for (int i = 0; i < 8; i++)
#pragma unroll
                for (int j = 0; j < 8; j++) acc[i][j] += a[i] * b[j];
        }
        __syncthreads();
    }
#pragma unroll
    for (int i = 0; i < 8; i++) {
        int row = m0 + ty * 8 + i;
        if (row >= M) continue;
#pragma unroll
        for (int j = 0; j < 8; j++) {
            int col = tx * 8 + j;
            float v = acc[i][j] + bias[col];
            if (MODE == 0) {
                v = fmaxf(v, 0.f);
            } else {
                float pv = P[(size_t)row * HID + col];
                float qv = Q[(size_t)row * HID + col];
                v = v * pv + (1.f - v) * qv;
            }
            C[(size_t)row * HID + col] = v;
        }
    }
}

// ---------------------------------------------------------------------------
// gate finalize: g = sigmoid(h2 . W3 + b3); v = g*f + (1-g)*emb[nid]
// one warp per node
// ---------------------------------------------------------------------------
__global__ void gate_fin_kernel(const float* __restrict__ h2,
                                const float* __restrict__ W3,
                                const float* __restrict__ b3,
                                const float* __restrict__ f,
                                const float* __restrict__ emb,
                                const int* __restrict__ nid,
                                float* __restrict__ v_out)
{
    int w = (blockIdx.x * blockDim.x + threadIdx.x) >> 5;
    int lane = threadIdx.x & 31;
    if (w >= NN) return;
    float4 h4 = *(const float4*)(h2 + (size_t)w * HID + lane * 4);
    float4 w4 = *(const float4*)(W3 + lane * 4);
    float d = h4.x * w4.x + h4.y * w4.y + h4.z * w4.z + h4.w * w4.w;
#pragma unroll
    for (int o = 16; o; o >>= 1) d += __shfl_xor_sync(0xffffffffu, d, o);
    float g = 1.f / (1.f + expf(-(d + b3[0])));
    int e = nid[w];
    float4 fv = *(const float4*)(f + (size_t)w * HID + lane * 4);
    float4 ev = *(const float4*)(emb + (size_t)e * HID + lane * 4);
    float4 o4;
    o4.x = g * fv.x + (1.f - g) * ev.x;
    o4.y = g * fv.y + (1.f - g) * ev.y;
    o4.z = g * fv.z + (1.f - g) * ev.z;
    o4.w = g * fv.w + (1.f - g) * ev.w;
    *(float4*)(v_out + (size_t)w * HID + lane * 4) = o4;
}

// e_src = z . a1, e_dst = z . a2  (one warp per node)
__global__ void attn_e_kernel(const float* __restrict__ z,
                              const float* __restrict__ a,
                              float* __restrict__ es, float* __restrict__ ed)
{
    int w = (blockIdx.x * blockDim.x + threadIdx.x) >> 5;
    int lane = threadIdx.x & 31;
    if (w >= NN) return;
    float4 zv = *(const float4*)(z + (size_t)w * HID + lane * 4);
    float4 a1 = *(const float4*)(a + lane * 4);
    float4 a2 = *(const float4*)(a + HID + lane * 4);
    float d1 = zv.x * a1.x + zv.y * a1.y + zv.z * a1.z + zv.w * a1.w;
    float d2 = zv.x * a2.x + zv.y * a2.y + zv.z * a2.z + zv.w * a2.w;
#pragma unroll
    for (int o = 16; o; o >>= 1) {
        d1 += __shfl_xor_sync(0xffffffffu, d1, o);
        d2 += __shfl_xor_sync(0xffffffffu, d2, o);
    }
    if (lane == 0) { es[w] = d1; ed[w] = d2; }
}

__global__ void init_kernel(float* __restrict__ out)
{
    int i = blockIdx.x * blockDim.x + threadIdx.x;
    if (i < NN * HID) out[i] = 0.f;
    if (i < NN) { g_emax[i] = ENC_NEG_INF; g_denom[i] = 0.f; }
}

__global__ void edge1_kernel(const int* __restrict__ src, const int* __restrict__ dst)
{
    int e = blockIdx.x * blockDim.x + threadIdx.x;
    if (e >= NE) return;
    int d = dst[e];
    float v = g_esrc[src[e]] + g_edst[d];
    v = (v > 0.f) ? v : 0.01f * v;
    g_e[e] = v;
    atomicMax(&g_emax[d], fenc(v));
}

// one warp per edge: w = exp(e - emax[dst]); denom[dst]+=w; out[dst] += w*z[src]
__global__ void edge2_kernel(const int* __restrict__ src, const int* __restrict__ dst,
                             float* __restrict__ out)
{
    int e = (blockIdx.x * blockDim.x + threadIdx.x) >> 5;
    int lane = threadIdx.x & 31;
    if (e >= NE) return;
    int s = src[e], d = dst[e];
    float w = expf(g_e[e] - fdec(g_emax[d]));
    if (lane == 0) atomicAdd(&g_denom[d], w);
    float4 zv = *(const float4*)(g_z + (size_t)s * HID + lane * 4);
    float* o = out + (size_t)d * HID + lane * 4;
    atomicAdd(o + 0, w * zv.x);
    atomicAdd(o + 1, w * zv.y);
    atomicAdd(o + 2, w * zv.z);
    atomicAdd(o + 3, w * zv.w);
}

__global__ void norm_kernel(float* __restrict__ out)
{
    int i = blockIdx.x * blockDim.x + threadIdx.x;
    if (i >= NN * HID) return;
    out[i] = out[i] / fmaxf(g_denom[i >> 7], 1e-20f);
}

// ---------------------------------------------------------------------------
extern "C" void kernel_launch(void* const* d_in, const int* in_sizes, int n_in,
                              void* d_out, int out_size)
{
    const int*   node_id = (const int*)  d_in[0];
    const float* img_h   = (const float*)d_in[1];
    const float* txt_h   = (const float*)d_in[2];
    const int*   src     = (const int*)  d_in[3];
    const int*   dst     = (const int*)  d_in[4];
    const float* emb     = (const float*)d_in[5];
    const float* W_img   = (const float*)d_in[6];
    const float* img_W1  = (const float*)d_in[7];
    const float* img_b1  = (const float*)d_in[8];
    const float* img_W2  = (const float*)d_in[9];
    const float* img_b2  = (const float*)d_in[10];
    const float* img_W3  = (const float*)d_in[11];
    const float* img_b3  = (const float*)d_in[12];
    const float* W_txt   = (const float*)d_in[13];
    const float* txt_W1  = (const float*)d_in[14];
    const float* txt_b1  = (const float*)d_in[15];
    const float* txt_W2  = (const float*)d_in[16];
    const float* txt_b2  = (const float*)d_in[17];
    const float* txt_W3  = (const float*)d_in[18];
    const float* txt_b3  = (const float*)d_in[19];
    const float* comb_W  = (const float*)d_in[20];
    const float* comb_b  = (const float*)d_in[21];
    const float* fc_W    = (const float*)d_in[22];
    const float* attn_a  = (const float*)d_in[23];
    float* out = (float*)d_out;

    float *imgf, *txtf, *h1, *h2, *imgv, *txtv, *hb, *zb, *es, *ed;
    cudaGetSymbolAddress((void**)&imgf, g_img_f);
    cudaGetSymbolAddress((void**)&txtf, g_txt_f);
    cudaGetSymbolAddress((void**)&h1,   g_h1);
    cudaGetSymbolAddress((void**)&h2,   g_h2);
    cudaGetSymbolAddress((void**)&imgv, g_img_v);
    cudaGetSymbolAddress((void**)&txtv, g_txt_v);
    cudaGetSymbolAddress((void**)&hb,   g_hbuf);
    cudaGetSymbolAddress((void**)&zb,   g_z);
    cudaGetSymbolAddress((void**)&es,   g_esrc);
    cudaGetSymbolAddress((void**)&ed,   g_edst);

    const int GB = (NN + 127) / 128;          // 391 tile-rows
    const int WARP_BLKS = (NN * 32 + 255) / 256;

    // feature projections
    gemm_dense<false, false><<<GB, 256>>>(img_h, W_img, nullptr, imgf, NN, 2048);
    gemm_dense<false, false><<<GB, 256>>>(txt_h, W_txt, nullptr, txtf, NN, 768);

    // img gate path
    gemm_cat<0><<<GB, 256>>>(emb, imgf, node_id, img_W1, img_b1, h1, NN);
    gemm_dense<true, true><<<GB, 256>>>(h1, img_W2, img_b2, h2, NN, 128);
    gate_fin_kernel<<<WARP_BLKS, 256>>>(h2, img_W3, img_b3, imgf, emb, node_id, imgv);

    // txt gate path
    gemm_cat<0><<<GB, 256>>>(emb, txtf, node_id, txt_W1, txt_b1, h1, NN);
    gemm_dense<true, true><<<GB, 256>>>(h1, txt_W2, txt_b2, h2, NN, 128);
    gate_fin_kernel<<<WARP_BLKS, 256>>>(h2, txt_W3, txt_b3, txtf, emb, node_id, txtv);

    // combine + fc
    gemm_cat<1><<<GB, 256>>>(imgv, txtv, nullptr, comb_W, comb_b, hb, NN);
    gemm_dense<false, false><<<GB, 256>>>(hb, fc_W, nullptr, zb, NN, 128);

    // attention scalars
    attn_e_kernel<<<WARP_BLKS, 256>>>(zb, attn_a, es, ed);

    // edge softmax + aggregate
    init_kernel<<<(NN * HID + 255) / 256, 256>>>(out);
    edge1_kernel<<<(NE + 255) / 256, 256>>>(src, dst);
    edge2_kernel<<<(NE * 32 + 255) / 256, 256>>>(src, dst, out);
    norm_kernel<<<(NN * HID + 255) / 256, 256>>>(out);
}

// round 7
// speedup vs baseline: 2.0805x; 2.0805x over previous
#include <cuda_runtime.h>
#include <cstdint>

#define NN 50000
#define NE 800000
#define HID 128

// ---------------- scratch (static device arrays; no allocation) ----------------
__device__ float g_img_f[(size_t)NN * HID];
__device__ float g_txt_f[(size_t)NN * HID];
__device__ float g_h1   [(size_t)NN * HID];
__device__ float g_h2   [(size_t)NN * HID];
__device__ float g_img_v[(size_t)NN * HID];
__device__ float g_txt_v[(size_t)NN * HID];
__device__ float g_hbuf [(size_t)NN * HID];
__device__ float g_z    [(size_t)NN * HID];
__device__ float g_esrc [NN];
__device__ float g_edst [NN];
__device__ unsigned g_emax[NN];
__device__ float g_denom[NN];
__device__ float g_e    [NE];

// ordered encoding of float for atomicMax on unsigned
__device__ __forceinline__ unsigned fenc(float f) {
    unsigned u = __float_as_uint(f);
    return (u & 0x80000000u) ? ~u : (u | 0x80000000u);
}
__device__ __forceinline__ float fdec(unsigned u) {
    return (u & 0x80000000u) ? __uint_as_float(u & 0x7FFFFFFFu)
                             : __uint_as_float(~u);
}
#define ENC_NEG_INF 0x007FFFFFu

// ---------------------------------------------------------------------------
// tf32 helpers
// ---------------------------------------------------------------------------
__device__ __forceinline__ uint32_t f2tf(float f) {
    uint32_t r;
    asm("cvt.rna.tf32.f32 %0, %1;" : "=r"(r) : "f"(f));
    return r;
}

__device__ __forceinline__ void mma_tf32(float* c,
                                         uint32_t a0, uint32_t a1, uint32_t a2, uint32_t a3,
                                         uint32_t b0, uint32_t b1)
{
    asm volatile(
        "mma.sync.aligned.m16n8k8.row.col.f32.tf32.tf32.f32 "
        "{%0,%1,%2,%3},{%4,%5,%6,%7},{%8,%9},{%0,%1,%2,%3};"
        : "+f"(c[0]), "+f"(c[1]), "+f"(c[2]), "+f"(c[3])
        : "r"(a0), "r"(a1), "r"(a2), "r"(a3), "r"(b0), "r"(b1));
}

// SMEM layout: As[k 0..31][m 0..127] stride 136 (==8 mod 32):
//   fragment loads: bank = ((k&3)*8 + (m&7)) mod 32 -> conflict-free.
#define TCSTRIDE 136

// ---------------------------------------------------------------------------
// tensor-core SGEMM (tf32): C[M x 128] = act(A[M x K] @ B[K x 128] (+bias))
// block tile 128x128, BK=32, 256 threads = 8 warps (2x4), warp tile 64x32
// ---------------------------------------------------------------------------
template<bool BIAS, bool RELU>
__global__ __launch_bounds__(256, 2)
void gemm_tc(const float* __restrict__ A, const float* __restrict__ B,
             const float* __restrict__ bias, float* __restrict__ C,
             int M, int K)
{
    __shared__ uint32_t As[32][TCSTRIDE];
    __shared__ uint32_t Bs[32][TCSTRIDE];

    const int tid  = threadIdx.x;
    const int warp = tid >> 5;
    const int lane = tid & 31;
    const int m0   = blockIdx.x * 128;

    const int wmb = (warp & 1) * 64;   // warp M offset
    const int wnb = (warp >> 1) * 32;  // warp N offset

    // A loader mapping: k-group g=0..7 (4 cols), rows via lane pairs (32B sectors)
    const int akc = (((warp & 3) << 1) | (lane & 1)) << 2;      // 0,4,...,28
    const int arb = ((warp >> 2) << 4) | (lane >> 1);           // 0..31
    // B loader: warp -> k-row, lanes -> 128 n (float4)
    const int bn  = lane << 2;

    float acc[4][4][4];
#pragma unroll
    for (int i = 0; i < 4; i++)
#pragma unroll
        for (int j = 0; j < 4; j++)
#pragma unroll
            for (int v = 0; v < 4; v++) acc[i][j][v] = 0.f;

    for (int k0 = 0; k0 < K; k0 += 32) {
        // ---- load A tile (tf32 convert at store) ----
#pragma unroll
        for (int p = 0; p < 4; p++) {
            int row = arb + p * 32;
            int gr  = m0 + row;
            float4 v = make_float4(0.f, 0.f, 0.f, 0.f);
            if (gr < M) v = *(const float4*)(A + (size_t)gr * K + k0 + akc);
            As[akc + 0][row] = f2tf(v.x);
            As[akc + 1][row] = f2tf(v.y);
            As[akc + 2][row] = f2tf(v.z);
            As[akc + 3][row] = f2tf(v.w);
        }
        // ---- load B tile ----
#pragma unroll
        for (int p = 0; p < 4; p++) {
            int k = warp + p * 8;
            float4 v = *(const float4*)(B + (size_t)(k0 + k) * HID + bn);
            uint4 u;
            u.x = f2tf(v.x); u.y = f2tf(v.y); u.z = f2tf(v.z); u.w = f2tf(v.w);
            *(uint4*)&Bs[k][bn] = u;
        }
        __syncthreads();

        // ---- compute ----
#pragma unroll
        for (int ks = 0; ks < 4; ks++) {
            const int ak  = ks * 8 + (lane & 3);
            const int amb = wmb + (lane >> 2);
            const int bnb = wnb + (lane >> 2);
            uint32_t af[4][4], bf[4][2];
#pragma unroll
            for (int mt = 0; mt < 4; mt++) {
                af[mt][0] = As[ak    ][amb + mt * 16    ];
                af[mt][1] = As[ak    ][amb + mt * 16 + 8];
                af[mt][2] = As[ak + 4][amb + mt * 16    ];
                af[mt][3] = As[ak + 4][amb + mt * 16 + 8];
            }
#pragma unroll
            for (int nt = 0; nt < 4; nt++) {
                bf[nt][0] = Bs[ak    ][bnb + nt * 8];
                bf[nt][1] = Bs[ak + 4][bnb + nt * 8];
            }
#pragma unroll
            for (int mt = 0; mt < 4; mt++)
#pragma unroll
                for (int nt = 0; nt < 4; nt++)
                    mma_tf32(acc[mt][nt], af[mt][0], af[mt][1], af[mt][2], af[mt][3],
                             bf[nt][0], bf[nt][1]);
        }
        __syncthreads();
    }

    // ---- epilogue ----
#pragma unroll
    for (int mt = 0; mt < 4; mt++) {
        int r0 = m0 + wmb + mt * 16 + (lane >> 2);
#pragma unroll
        for (int nt = 0; nt < 4; nt++) {
            int c = wnb + nt * 8 + ((lane & 3) << 1);
            float bb0 = 0.f, bb1 = 0.f;
            if (BIAS) { bb0 = bias[c]; bb1 = bias[c + 1]; }
            float v0 = acc[mt][nt][0] + bb0, v1 = acc[mt][nt][1] + bb1;
            float v2 = acc[mt][nt][2] + bb0, v3 = acc[mt][nt][3] + bb1;
            if (RELU) {
                v0 = fmaxf(v0, 0.f); v1 = fmaxf(v1, 0.f);
                v2 = fmaxf(v2, 0.f); v3 = fmaxf(v3, 0.f);
            }
            if (r0 < M)     *(float2*)(C + (size_t)r0 * HID + c)       = make_float2(v0, v1);
            if (r0 + 8 < M) *(float2*)(C + (size_t)(r0 + 8) * HID + c) = make_float2(v2, v3);
        }
    }
}

// ---------------------------------------------------------------------------
// tensor-core concat SGEMM: A row r = [ P[gidx?gidx[r]:r] (128) | Q[r] (128) ]
// MODE 0: C = relu(A@B + bias)                        (gate MLP layer 1)
// MODE 1: gate = A@B + bias; C = gate*P + (1-gate)*Q  (comb combine, no gather)
// ---------------------------------------------------------------------------
template<int MODE>
__global__ __launch_bounds__(256, 2)
void gemm_tc_cat(const float* __restrict__ P, const float* __restrict__ Q,
                 const int* __restrict__ gidx,
                 const float* __restrict__ B, const float* __restrict__ bias,
                 float* __restrict__ C, int M)
{
    __shared__ uint32_t As[32][TCSTRIDE];
    __shared__ uint32_t Bs[32][TCSTRIDE];

    const int tid  = threadIdx.x;
    const int warp = tid >> 5;
    const int lane = tid & 31;
    const int m0   = blockIdx.x * 128;

    const int wmb = (warp & 1) * 64;
    const int wnb = (warp >> 1) * 32;

    const int akc = (((warp & 3) << 1) | (lane & 1)) << 2;
    const int arb = ((warp >> 2) << 4) | (lane >> 1);
    const int bn  = lane << 2;

    float acc[4][4][4];
#pragma unroll
    for (int i = 0; i < 4; i++)
#pragma unroll
        for (int j = 0; j < 4; j++)
#pragma unroll
            for (int v = 0; v < 4; v++) acc[i][j][v] = 0.f;

    for (int k0 = 0; k0 < 256; k0 += 32) {
        const float* S   = (k0 < 128) ? P : Q;
        const int cbase  = (k0 < 128) ? k0 : (k0 - 128);
        const bool gather = (MODE == 0) && (k0 < 128);
#pragma unroll
        for (int p = 0; p < 4; p++) {
            int row = arb + p * 32;
            int gr  = m0 + row;
            float4 v = make_float4(0.f, 0.f, 0.f, 0.f);
            if (gr < M) {
                int rr = gather ? gidx[gr] : gr;
                v = *(const float4*)(S + (size_t)rr * HID + cbase + akc);
            }
            As[akc + 0][row] = f2tf(v.x);
            As[akc + 1][row] = f2tf(v.y);
            As[akc + 2][row] = f2tf(v.z);
            As[akc + 3][row] = f2tf(v.w);
        }
#pragma unroll
        for (int p = 0; p < 4; p++) {
            int k = warp + p * 8;
            float4 v = *(const float4*)(B + (size_t)(k0 + k) * HID + bn);
            uint4 u;
            u.x = f2tf(v.x); u.y = f2tf(v.y); u.z = f2tf(v.z); u.w = f2tf(v.w);
            *(uint4*)&Bs[k][bn] = u;
        }
        __syncthreads();

#pragma unroll
        for (int ks = 0; ks < 4; ks++) {
            const int ak  = ks * 8 + (lane & 3);
            const int amb = wmb + (lane >> 2);
            const int bnb = wnb + (lane >> 2);
            uint32_t af[4][4], bf[4][2];
#pragma unroll
            for (int mt = 0; mt < 4; mt++) {
                af[mt][0] = As[ak    ][amb + mt * 16    ];
                af[mt][1] = As[ak    ][amb + mt * 16 + 8];
                af[mt][2] = As[ak + 4][amb + mt * 16    ];
                af[mt][3] = As[ak + 4][amb + mt * 16 + 8];
            }
#pragma unroll
            for (int nt = 0; nt < 4; nt++) {
                bf[nt][0] = Bs[ak    ][bnb + nt * 8];
                bf[nt][1] = Bs[ak + 4][bnb + nt * 8];
            }
#pragma unroll
            for (int mt = 0; mt < 4; mt++)
#pragma unroll
                for (int nt = 0; nt < 4; nt++)
                    mma_tf32(acc[mt][nt], af[mt][0], af[mt][1], af[mt][2], af[mt][3],
                             bf[nt][0], bf[nt][1]);
        }
        __syncthreads();
    }

#pragma unroll
    for (int mt = 0; mt < 4; mt++) {
        int r0 = m0 + wmb + mt * 16 + (lane >> 2);
#pragma unroll
        for (int nt = 0; nt < 4; nt++) {
            int c = wnb + nt * 8 + ((lane & 3) << 1);
            float bb0 = bias[c], bb1 = bias[c + 1];
            float v0 = acc[mt][nt][0] + bb0, v1 = acc[mt][nt][1] + bb1;
            float v2 = acc[mt][nt][2] + bb0, v3 = acc[mt][nt][3] + bb1;
#pragma unroll
            for (int h = 0; h < 2; h++) {
                int r = r0 + h * 8;
                if (r >= M) continue;
                float g0 = h ? v2 : v0, g1 = h ? v3 : v1;
                float o0, o1;
                if (MODE == 0) {
                    o0 = fmaxf(g0, 0.f);
                    o1 = fmaxf(g1, 0.f);
                } else {
                    float2 pv = *(const float2*)(P + (size_t)r * HID + c);
                    float2 qv = *(const float2*)(Q + (size_t)r * HID + c);
                    o0 = g0 * pv.x + (1.f - g0) * qv.x;
                    o1 = g1 * pv.y + (1.f - g1) * qv.y;
                }
                *(float2*)(C + (size_t)r * HID + c) = make_float2(o0, o1);
            }
        }
    }
}

// ---------------------------------------------------------------------------
// gate finalize: g = sigmoid(h2 . W3 + b3); v = g*f + (1-g)*emb[nid]
// ---------------------------------------------------------------------------
__global__ void gate_fin_kernel(const float* __restrict__ h2,
                                const float* __restrict__ W3,
                                const float* __restrict__ b3,
                                const float* __restrict__ f,
                                const float* __restrict__ emb,
                                const int* __restrict__ nid,
                                float* __restrict__ v_out)
{
    int w = (blockIdx.x * blockDim.x + threadIdx.x) >> 5;
    int lane = threadIdx.x & 31;
    if (w >= NN) return;
    float4 h4 = *(const float4*)(h2 + (size_t)w * HID + lane * 4);
    float4 w4 = *(const float4*)(W3 + lane * 4);
    float d = h4.x * w4.x + h4.y * w4.y + h4.z * w4.z + h4.w * w4.w;
#pragma unroll
    for (int o = 16; o; o >>= 1) d += __shfl_xor_sync(0xffffffffu, d, o);
    float g = 1.f / (1.f + expf(-(d + b3[0])));
    int e = nid[w];
    float4 fv = *(const float4*)(f + (size_t)w * HID + lane * 4);
    float4 ev = *(const float4*)(emb + (size_t)e * HID + lane * 4);
    float4 o4;
    o4.x = g * fv.x + (1.f - g) * ev.x;
    o4.y = g * fv.y + (1.f - g) * ev.y;
    o4.z = g * fv.z + (1.f - g) * ev.z;
    o4.w = g * fv.w + (1.f - g) * ev.w;
    *(float4*)(v_out + (size_t)w * HID + lane * 4) = o4;
}

// e_src = z . a1, e_dst = z . a2  (one warp per node)
__global__ void attn_e_kernel(const float* __restrict__ z,
                              const float* __restrict__ a,
                              float* __restrict__ es, float* __restrict__ ed)
{
    int w = (blockIdx.x * blockDim.x + threadIdx.x) >> 5;
    int lane = threadIdx.x & 31;
    if (w >= NN) return;
    float4 zv = *(const float4*)(z + (size_t)w * HID + lane * 4);
    float4 a1 = *(const float4*)(a + lane * 4);
    float4 a2 = *(const float4*)(a + HID + lane * 4);
    float d1 = zv.x * a1.x + zv.y * a1.y + zv.z * a1.z + zv.w * a1.w;
    float d2 = zv.x * a2.x + zv.y * a2.y + zv.z * a2.z + zv.w * a2.w;
#pragma unroll
    for (int o = 16; o; o >>= 1) {
        d1 += __shfl_xor_sync(0xffffffffu, d1, o);
        d2 += __shfl_xor_sync(0xffffffffu, d2, o);
    }
    if (lane == 0) { es[w] = d1; ed[w] = d2; }
}

__global__ void init_kernel(float* __restrict__ out)
{
    int i = blockIdx.x * blockDim.x + threadIdx.x;
    if (i < NN * HID) out[i] = 0.f;
    if (i < NN) { g_emax[i] = ENC_NEG_INF; g_denom[i] = 0.f; }
}

__global__ void edge1_kernel(const int* __restrict__ src, const int* __restrict__ dst)
{
    int e = blockIdx.x * blockDim.x + threadIdx.x;
    if (e >= NE) return;
    int d = dst[e];
    float v = g_esrc[src[e]] + g_edst[d];
    v = (v > 0.f) ? v : 0.01f * v;
    g_e[e] = v;
    atomicMax(&g_emax[d], fenc(v));
}

// one warp per edge: w = exp(e - emax[dst]); denom[dst]+=w; out[dst] += w*z[src]
__global__ void edge2_kernel(const int* __restrict__ src, const int* __restrict__ dst,
                             float* __restrict__ out)
{
    int e = (blockIdx.x * blockDim.x + threadIdx.x) >> 5;
    int lane = threadIdx.x & 31;
    if (e >= NE) return;
    int s = src[e], d = dst[e];
    float w = expf(g_e[e] - fdec(g_emax[d]));
    if (lane == 0) atomicAdd(&g_denom[d], w);
    float4 zv = *(const float4*)(g_z + (size_t)s * HID + lane * 4);
    float* o = out + (size_t)d * HID + lane * 4;
    atomicAdd(o + 0, w * zv.x);
    atomicAdd(o + 1, w * zv.y);
    atomicAdd(o + 2, w * zv.z);
    atomicAdd(o + 3, w * zv.w);
}

__global__ void norm_kernel(float* __restrict__ out)
{
    int i = blockIdx.x * blockDim.x + threadIdx.x;
    if (i >= NN * HID) return;
    out[i] = out[i] / fmaxf(g_denom[i >> 7], 1e-20f);
}

// ---------------------------------------------------------------------------
extern "C" void kernel_launch(void* const* d_in, const int* in_sizes, int n_in,
                              void* d_out, int out_size)
{
    const int*   node_id = (const int*)  d_in[0];
    const float* img_h   = (const float*)d_in[1];
    const float* txt_h   = (const float*)d_in[2];
    const int*   src     = (const int*)  d_in[3];
    const int*   dst     = (const int*)  d_in[4];
    const float* emb     = (const float*)d_in[5];
    const float* W_img   = (const float*)d_in[6];
    const float* img_W1  = (const float*)d_in[7];
    const float* img_b1  = (const float*)d_in[8];
    const float* img_W2  = (const float*)d_in[9];
    const float* img_b2  = (const float*)d_in[10];
    const float* img_W3  = (const float*)d_in[11];
    const float* img_b3  = (const float*)d_in[12];
    const float* W_txt   = (const float*)d_in[13];
    const float* txt_W1  = (const float*)d_in[14];
    const float* txt_b1  = (const float*)d_in[15];
    const float* txt_W2  = (const float*)d_in[16];
    const float* txt_b2  = (const float*)d_in[17];
    const float* txt_W3  = (const float*)d_in[18];
    const float* txt_b3  = (const float*)d_in[19];
    const float* comb_W  = (const float*)d_in[20];
    const float* comb_b  = (const float*)d_in[21];
    const float* fc_W    = (const float*)d_in[22];
    const float* attn_a  = (const float*)d_in[23];
    float* out = (float*)d_out;

    float *imgf, *txtf, *h1, *h2, *imgv, *txtv, *hb, *zb, *es, *ed;
    cudaGetSymbolAddress((void**)&imgf, g_img_f);
    cudaGetSymbolAddress((void**)&txtf, g_txt_f);
    cudaGetSymbolAddress((void**)&h1,   g_h1);
    cudaGetSymbolAddress((void**)&h2,   g_h2);
    cudaGetSymbolAddress((void**)&imgv, g_img_v);
    cudaGetSymbolAddress((void**)&txtv, g_txt_v);
    cudaGetSymbolAddress((void**)&hb,   g_hbuf);
    cudaGetSymbolAddress((void**)&zb,   g_z);
    cudaGetSymbolAddress((void**)&es,   g_esrc);
    cudaGetSymbolAddress((void**)&ed,   g_edst);

    const int GB = (NN + 127) / 128;          // 391 tile-rows
    const int WARP_BLKS = (NN * 32 + 255) / 256;

    // feature projections (tensor cores, tf32)
    gemm_tc<false, false><<<GB, 256>>>(img_h, W_img, nullptr, imgf, NN, 2048);
    gemm_tc<false, false><<<GB, 256>>>(txt_h, W_txt, nullptr, txtf, NN, 768);

    // img gate path
    gemm_tc_cat<0><<<GB, 256>>>(emb, imgf, node_id, img_W1, img_b1, h1, NN);
    gemm_tc<true, true><<<GB, 256>>>(h1, img_W2, img_b2, h2, NN, 128);
    gate_fin_kernel<<<WARP_BLKS, 256>>>(h2, img_W3, img_b3, imgf, emb, node_id, imgv);

    // txt gate path
    gemm_tc_cat<0><<<GB, 256>>>(emb, txtf, node_id, txt_W1, txt_b1, h1, NN);
    gemm_tc<true, true><<<GB, 256>>>(h1, txt_W2, txt_b2, h2, NN, 128);
    gate_fin_kernel<<<WARP_BLKS, 256>>>(h2, txt_W3, txt_b3, txtf, emb, node_id, txtv);

    // combine + fc
    gemm_tc_cat<1><<<GB, 256>>>(imgv, txtv, nullptr, comb_W, comb_b, hb, NN);
    gemm_tc<false, false><<<GB, 256>>>(hb, fc_W, nullptr, zb, NN, 128);

    // attention scalars
    attn_e_kernel<<<WARP_BLKS, 256>>>(zb, attn_a, es, ed);

    // edge softmax + aggregate
    init_kernel<<<(NN * HID + 255) / 256, 256>>>(out);
    edge1_kernel<<<(NE + 255) / 256, 256>>>(src, dst);
    edge2_kernel<<<(NE * 32 + 255) / 256, 256>>>(src, dst, out);
    norm_kernel<<<(NN * HID + 255) / 256, 256>>>(out);
}

// round 8
// speedup vs baseline: 2.9952x; 1.4397x over previous
#include <cuda_runtime.h>
#include <cstdint>

#define NN 50000
#define NE 800000
#define HID 128

// ---------------- scratch (static device arrays; no allocation) ----------------
__device__ float g_img_f[(size_t)NN * HID];
__device__ float g_txt_f[(size_t)NN * HID];
__device__ float g_h1   [(size_t)NN * HID];
__device__ float g_h2   [(size_t)NN * HID];
__device__ float g_img_v[(size_t)NN * HID];
__device__ float g_txt_v[(size_t)NN * HID];
__device__ float g_hbuf [(size_t)NN * HID];
__device__ float g_z    [(size_t)NN * HID];
__device__ float g_esrc [NN];
__device__ float g_edst [NN];
__device__ unsigned g_emax[NN];
__device__ float g_denom[NN];
__device__ float g_e    [NE];

// ordered encoding of float for atomicMax on unsigned
__device__ __forceinline__ unsigned fenc(float f) {
    unsigned u = __float_as_uint(f);
    return (u & 0x80000000u) ? ~u : (u | 0x80000000u);
}
__device__ __forceinline__ float fdec(unsigned u) {
    return (u & 0x80000000u) ? __uint_as_float(u & 0x7FFFFFFFu)
                             : __uint_as_float(~u);
}
#define ENC_NEG_INF 0x007FFFFFu

// ---------------------------------------------------------------------------
// tf32 / cp.async helpers
// ---------------------------------------------------------------------------
__device__ __forceinline__ uint32_t f2tf(float f) {
    uint32_t r;
    asm("cvt.rna.tf32.f32 %0, %1;" : "=r"(r) : "f"(f));
    return r;
}

__device__ __forceinline__ void mma_tf32(float* c,
                                         uint32_t a0, uint32_t a1, uint32_t a2, uint32_t a3,
                                         uint32_t b0, uint32_t b1)
{
    asm volatile(
        "mma.sync.aligned.m16n8k8.row.col.f32.tf32.tf32.f32 "
        "{%0,%1,%2,%3},{%4,%5,%6,%7},{%8,%9},{%0,%1,%2,%3};"
        : "+f"(c[0]), "+f"(c[1]), "+f"(c[2]), "+f"(c[3])
        : "r"(a0), "r"(a1), "r"(a2), "r"(a3), "r"(b0), "r"(b1));
}

__device__ __forceinline__ void cp16(uint32_t sdst, const void* gsrc, int predsz) {
    asm volatile("cp.async.cg.shared.global [%0], [%1], 16, %2;"
                 :: "r"(sdst), "l"(gsrc), "r"(predsz));
}
#define CP_COMMIT() asm volatile("cp.async.commit_group;")

// SMEM strides: As[m][20] -> bank (20g+c)%32 permutation; Bs[k][136] -> (8c+g)%32 perm.
#define ASTR 20
#define BSTR 136

// ---------------------------------------------------------------------------
// tensor-core SGEMM (tf32, cp.async double-buffered):
// C[M x 128] = act(A[M x K] @ B[K x 128] (+bias)), K % 16 == 0
// block tile 128x128, BK=16, 256 threads = 8 warps (2x4), warp tile 64x32
// ---------------------------------------------------------------------------
template<bool BIAS, bool RELU>
__global__ __launch_bounds__(256, 2)
void gemm_tc(const float* __restrict__ A, const float* __restrict__ B,
             const float* __restrict__ bias, float* __restrict__ C,
             int M, int K)
{
    __shared__ float As[2][128][ASTR];
    __shared__ float Bs[2][16][BSTR];

    const int tid  = threadIdx.x;
    const int warp = tid >> 5;
    const int lane = tid & 31;
    const int m0   = blockIdx.x * 128;

    const int wmb = (warp & 1) * 64;   // warp M offset
    const int wnb = (warp >> 1) * 32;  // warp N offset

    // loader indices
    const int ar0 = tid >> 2;          // A row 0..63 (+64 second chunk)
    const int ac0 = (tid & 3) << 2;    // A col group
    const int bn0 = (tid & 31) << 2;   // B n

    float acc[4][4][4];
#pragma unroll
    for (int i = 0; i < 4; i++)
#pragma unroll
        for (int j = 0; j < 4; j++)
#pragma unroll
            for (int v = 0; v < 4; v++) acc[i][j][v] = 0.f;

    auto load_tile = [&](int buf, int k0) {
#pragma unroll
        for (int p = 0; p < 2; p++) {
            int row = ar0 + p * 64;
            int gr  = m0 + row;
            cp16((uint32_t)__cvta_generic_to_shared(&As[buf][row][ac0]),
                 A + (size_t)gr * K + k0 + ac0, gr < M ? 16 : 0);
        }
#pragma unroll
        for (int p = 0; p < 2; p++) {
            int k = warp + p * 8;
            cp16((uint32_t)__cvta_generic_to_shared(&Bs[buf][k][bn0]),
                 B + (size_t)(k0 + k) * HID + bn0, 16);
        }
    };

    load_tile(0, 0);
    CP_COMMIT();

    const int T = K >> 4;
    for (int t = 0; t < T; t++) {
        const int buf = t & 1;
        if (t + 1 < T) {
            load_tile(buf ^ 1, (t + 1) << 4);
            CP_COMMIT();
            asm volatile("cp.async.wait_group 1;");
        } else {
            asm volatile("cp.async.wait_group 0;");
        }
        __syncthreads();

#pragma unroll
        for (int ks = 0; ks < 2; ks++) {
            const int kc = ks * 8 + (lane & 3);
            const int gm = lane >> 2;
            uint32_t af[4][4], bf[4][2];
#pragma unroll
            for (int mt = 0; mt < 4; mt++) {
                int m = wmb + mt * 16 + gm;
                af[mt][0] = f2tf(As[buf][m    ][kc    ]);
                af[mt][1] = f2tf(As[buf][m + 8][kc    ]);
                af[mt][2] = f2tf(As[buf][m    ][kc + 4]);
                af[mt][3] = f2tf(As[buf][m + 8][kc + 4]);
            }
#pragma unroll
            for (int nt = 0; nt < 4; nt++) {
                int n = wnb + nt * 8 + gm;
                bf[nt][0] = f2tf(Bs[buf][kc    ][n]);
                bf[nt][1] = f2tf(Bs[buf][kc + 4][n]);
            }
#pragma unroll
            for (int mt = 0; mt < 4; mt++)
#pragma unroll
                for (int nt = 0; nt < 4; nt++)
                    mma_tf32(acc[mt][nt], af[mt][0], af[mt][1], af[mt][2], af[mt][3],
                             bf[nt][0], bf[nt][1]);
        }
        __syncthreads();
    }

    // ---- epilogue ----
#pragma unroll
    for (int mt = 0; mt < 4; mt++) {
        int r0 = m0 + wmb + mt * 16 + (lane >> 2);
#pragma unroll
        for (int nt = 0; nt < 4; nt++) {
            int c = wnb + nt * 8 + ((lane & 3) << 1);
            float bb0 = 0.f, bb1 = 0.f;
            if (BIAS) { bb0 = bias[c]; bb1 = bias[c + 1]; }
            float v0 = acc[mt][nt][0] + bb0, v1 = acc[mt][nt][1] + bb1;
            float v2 = acc[mt][nt][2] + bb0, v3 = acc[mt][nt][3] + bb1;
            if (RELU) {
                v0 = fmaxf(v0, 0.f); v1 = fmaxf(v1, 0.f);
                v2 = fmaxf(v2, 0.f); v3 = fmaxf(v3, 0.f);
            }
            if (r0 < M)     *(float2*)(C + (size_t)r0 * HID + c)       = make_float2(v0, v1);
            if (r0 + 8 < M) *(float2*)(C + (size_t)(r0 + 8) * HID + c) = make_float2(v2, v3);
        }
    }
}

// ---------------------------------------------------------------------------
// tensor-core concat SGEMM (cp.async pipelined):
// A row r = [ P[gidx?gidx[r]:r] (128) | Q[r] (128) ], K = 256
// MODE 0: C = relu(A@B + bias)                        (gate MLP layer 1)
// MODE 1: gate = A@B + bias; C = gate*P + (1-gate)*Q  (comb combine, no gather)
// ---------------------------------------------------------------------------
template<int MODE>
__global__ __launch_bounds__(256, 2)
void gemm_tc_cat(const float* __restrict__ P, const float* __restrict__ Q,
                 const int* __restrict__ gidx,
                 const float* __restrict__ B, const float* __restrict__ bias,
                 float* __restrict__ C, int M)
{
    __shared__ float As[2][128][ASTR];
    __shared__ float Bs[2][16][BSTR];

    const int tid  = threadIdx.x;
    const int warp = tid >> 5;
    const int lane = tid & 31;
    const int m0   = blockIdx.x * 128;

    const int wmb = (warp & 1) * 64;
    const int wnb = (warp >> 1) * 32;

    const int ar0 = tid >> 2;
    const int ac0 = (tid & 3) << 2;
    const int bn0 = (tid & 31) << 2;

    // per-thread precomputed row indices (rows are k-invariant)
    int grow[2], rgat[2], pr[2];
#pragma unroll
    for (int p = 0; p < 2; p++) {
        int row = ar0 + p * 64;
        int gr  = m0 + row;
        grow[p] = gr;
        pr[p]   = (gr < M) ? 16 : 0;
        rgat[p] = (MODE == 0) ? ((gr < M) ? gidx[gr] : 0) : gr;
    }

    float acc[4][4][4];
#pragma unroll
    for (int i = 0; i < 4; i++)
#pragma unroll
        for (int j = 0; j < 4; j++)
#pragma unroll
            for (int v = 0; v < 4; v++) acc[i][j][v] = 0.f;

    auto load_tile = [&](int buf, int k0) {
        const float* S  = (k0 < 128) ? P : Q;
        const int cbase = (k0 < 128) ? k0 : (k0 - 128);
        const bool gath = (k0 < 128);
#pragma unroll
        for (int p = 0; p < 2; p++) {
            int row = ar0 + p * 64;
            int rr  = gath ? rgat[p] : grow[p];
            cp16((uint32_t)__cvta_generic_to_shared(&As[buf][row][ac0]),
                 S + (size_t)rr * HID + cbase + ac0, pr[p]);
        }
#pragma unroll
        for (int p = 0; p < 2; p++) {
            int k = warp + p * 8;
            cp16((uint32_t)__cvta_generic_to_shared(&Bs[buf][k][bn0]),
                 B + (size_t)(k0 + k) * HID + bn0, 16);
        }
    };

    load_tile(0, 0);
    CP_COMMIT();

    const int T = 16;  // K = 256
    for (int t = 0; t < T; t++) {
        const int buf = t & 1;
        if (t + 1 < T) {
            load_tile(buf ^ 1, (t + 1) << 4);
            CP_COMMIT();
            asm volatile("cp.async.wait_group 1;");
        } else {
            asm volatile("cp.async.wait_group 0;");
        }
        __syncthreads();

#pragma unroll
        for (int ks = 0; ks < 2; ks++) {
            const int kc = ks * 8 + (lane & 3);
            const int gm = lane >> 2;
            uint32_t af[4][4], bf[4][2];
#pragma unroll
            for (int mt = 0; mt < 4; mt++) {
                int m = wmb + mt * 16 + gm;
                af[mt][0] = f2tf(As[buf][m    ][kc    ]);
                af[mt][1] = f2tf(As[buf][m + 8][kc    ]);
                af[mt][2] = f2tf(As[buf][m    ][kc + 4]);
                af[mt][3] = f2tf(As[buf][m + 8][kc + 4]);
            }
#pragma unroll
            for (int nt = 0; nt < 4; nt++) {
                int n = wnb + nt * 8 + gm;
                bf[nt][0] = f2tf(Bs[buf][kc    ][n]);
                bf[nt][1] = f2tf(Bs[buf][kc + 4][n]);
            }
#pragma unroll
            for (int mt = 0; mt < 4; mt++)
#pragma unroll
                for (int nt = 0; nt < 4; nt++)
                    mma_tf32(acc[mt][nt], af[mt][0], af[mt][1], af[mt][2], af[mt][3],
                             bf[nt][0], bf[nt][1]);
        }
        __syncthreads();
    }

#pragma unroll
    for (int mt = 0; mt < 4; mt++) {
        int r0 = m0 + wmb + mt * 16 + (lane >> 2);
#pragma unroll
        for (int nt = 0; nt < 4; nt++) {
            int c = wnb + nt * 8 + ((lane & 3) << 1);
            float bb0 = bias[c], bb1 = bias[c + 1];
            float v0 = acc[mt][nt][0] + bb0, v1 = acc[mt][nt][1] + bb1;
            float v2 = acc[mt][nt][2] + bb0, v3 = acc[mt][nt][3] + bb1;
#pragma unroll
            for (int h = 0; h < 2; h++) {
                int r = r0 + h * 8;
                if (r >= M) continue;
                float g0 = h ? v2 : v0, g1 = h ? v3 : v1;
                float o0, o1;
                if (MODE == 0) {
                    o0 = fmaxf(g0, 0.f);
                    o1 = fmaxf(g1, 0.f);
                } else {
                    float2 pv = *(const float2*)(P + (size_t)r * HID + c);
                    float2 qv = *(const float2*)(Q + (size_t)r * HID + c);
                    o0 = g0 * pv.x + (1.f - g0) * qv.x;
                    o1 = g1 * pv.y + (1.f - g1) * qv.y;
                }
                *(float2*)(C + (size_t)r * HID + c) = make_float2(o0, o1);
            }
        }
    }
}

// ---------------------------------------------------------------------------
// gate finalize: g = sigmoid(h2 . W3 + b3); v = g*f + (1-g)*emb[nid]
// ---------------------------------------------------------------------------
__global__ void gate_fin_kernel(const float* __restrict__ h2,
                                const float* __restrict__ W3,
                                const float* __restrict__ b3,
                                const float* __restrict__ f,
                                const float* __restrict__ emb,
                                const int* __restrict__ nid,
                                float* __restrict__ v_out)
{
    int w = (blockIdx.x * blockDim.x + threadIdx.x) >> 5;
    int lane = threadIdx.x & 31;
    if (w >= NN) return;
    float4 h4 = *(const float4*)(h2 + (size_t)w * HID + lane * 4);
    float4 w4 = *(const float4*)(W3 + lane * 4);
    float d = h4.x * w4.x + h4.y * w4.y + h4.z * w4.z + h4.w * w4.w;
#pragma unroll
    for (int o = 16; o; o >>= 1) d += __shfl_xor_sync(0xffffffffu, d, o);
    float g = 1.f / (1.f + expf(-(d + b3[0])));
    int e = nid[w];
    float4 fv = *(const float4*)(f + (size_t)w * HID + lane * 4);
    float4 ev = *(const float4*)(emb + (size_t)e * HID + lane * 4);
    float4 o4;
    o4.x = g * fv.x + (1.f - g) * ev.x;
    o4.y = g * fv.y + (1.f - g) * ev.y;
    o4.z = g * fv.z + (1.f - g) * ev.z;
    o4.w = g * fv.w + (1.f - g) * ev.w;
    *(float4*)(v_out + (size_t)w * HID + lane * 4) = o4;
}

// e_src = z . a1, e_dst = z . a2  (one warp per node)
__global__ void attn_e_kernel(const float* __restrict__ z,
                              const float* __restrict__ a,
                              float* __restrict__ es, float* __restrict__ ed)
{
    int w = (blockIdx.x * blockDim.x + threadIdx.x) >> 5;
    int lane = threadIdx.x & 31;
    if (w >= NN) return;
    float4 zv = *(const float4*)(z + (size_t)w * HID + lane * 4);
    float4 a1 = *(const float4*)(a + lane * 4);
    float4 a2 = *(const float4*)(a + HID + lane * 4);
    float d1 = zv.x * a1.x + zv.y * a1.y + zv.z * a1.z + zv.w * a1.w;
    float d2 = zv.x * a2.x + zv.y * a2.y + zv.z * a2.z + zv.w * a2.w;
#pragma unroll
    for (int o = 16; o; o >>= 1) {
        d1 += __shfl_xor_sync(0xffffffffu, d1, o);
        d2 += __shfl_xor_sync(0xffffffffu, d2, o);
    }
    if (lane == 0) { es[w] = d1; ed[w] = d2; }
}

__global__ void init_kernel(float* __restrict__ out)
{
    int i = blockIdx.x * blockDim.x + threadIdx.x;
    if (i < NN * HID) out[i] = 0.f;
    if (i < NN) { g_emax[i] = ENC_NEG_INF; g_denom[i] = 0.f; }
}

__global__ void edge1_kernel(const int* __restrict__ src, const int* __restrict__ dst)
{
    int e = blockIdx.x * blockDim.x + threadIdx.x;
    if (e >= NE) return;
    int d = dst[e];
    float v = g_esrc[src[e]] + g_edst[d];
    v = (v > 0.f) ? v : 0.01f * v;
    g_e[e] = v;
    atomicMax(&g_emax[d], fenc(v));
}

// one warp per edge: w = exp(e - emax[dst]); denom[dst]+=w; out[dst] += w*z[src]
// vectorized v4 reduction (sm_90+) cuts atomic instruction count 4x
__global__ void edge2_kernel(const int* __restrict__ src, const int* __restrict__ dst,
                             float* __restrict__ out)
{
    int e = (blockIdx.x * blockDim.x + threadIdx.x) >> 5;
    int lane = threadIdx.x & 31;
    if (e >= NE) return;
    int s = src[e], d = dst[e];
    float w = expf(g_e[e] - fdec(g_emax[d]));
    if (lane == 0) atomicAdd(&g_denom[d], w);
    float4 zv = *(const float4*)(g_z + (size_t)s * HID + lane * 4);
    float* o = out + (size_t)d * HID + lane * 4;
    asm volatile("red.global.add.v4.f32 [%0], {%1, %2, %3, %4};"
                 :: "l"(o), "f"(w * zv.x), "f"(w * zv.y), "f"(w * zv.z), "f"(w * zv.w)
                 : "memory");
}

__global__ void norm_kernel(float* __restrict__ out)
{
    int i = blockIdx.x * blockDim.x + threadIdx.x;
    if (i >= NN * HID) return;
    out[i] = out[i] / fmaxf(g_denom[i >> 7], 1e-20f);
}

// ---------------------------------------------------------------------------
extern "C" void kernel_launch(void* const* d_in, const int* in_sizes, int n_in,
                              void* d_out, int out_size)
{
    const int*   node_id = (const int*)  d_in[0];
    const float* img_h   = (const float*)d_in[1];
    const float* txt_h   = (const float*)d_in[2];
    const int*   src     = (const int*)  d_in[3];
    const int*   dst     = (const int*)  d_in[4];
    const float* emb     = (const float*)d_in[5];
    const float* W_img   = (const float*)d_in[6];
    const float* img_W1  = (const float*)d_in[7];
    const float* img_b1  = (const float*)d_in[8];
    const float* img_W2  = (const float*)d_in[9];
    const float* img_b2  = (const float*)d_in[10];
    const float* img_W3  = (const float*)d_in[11];
    const float* img_b3  = (const float*)d_in[12];
    const float* W_txt   = (const float*)d_in[13];
    const float* txt_W1  = (const float*)d_in[14];
    const float* txt_b1  = (const float*)d_in[15];
    const float* txt_W2  = (const float*)d_in[16];
    const float* txt_b2  = (const float*)d_in[17];
    const float* txt_W3  = (const float*)d_in[18];
    const float* txt_b3  = (const float*)d_in[19];
    const float* comb_W  = (const float*)d_in[20];
    const float* comb_b  = (const float*)d_in[21];
    const float* fc_W    = (const float*)d_in[22];
    const float* attn_a  = (const float*)d_in[23];
    float* out = (float*)d_out;

    float *imgf, *txtf, *h1, *h2, *imgv, *txtv, *hb, *zb, *es, *ed;
    cudaGetSymbolAddress((void**)&imgf, g_img_f);
    cudaGetSymbolAddress((void**)&txtf, g_txt_f);
    cudaGetSymbolAddress((void**)&h1,   g_h1);
    cudaGetSymbolAddress((void**)&h2,   g_h2);
    cudaGetSymbolAddress((void**)&imgv, g_img_v);
    cudaGetSymbolAddress((void**)&txtv, g_txt_v);
    cudaGetSymbolAddress((void**)&hb,   g_hbuf);
    cudaGetSymbolAddress((void**)&zb,   g_z);
    cudaGetSymbolAddress((void**)&es,   g_esrc);
    cudaGetSymbolAddress((void**)&ed,   g_edst);

    const int GB = (NN + 127) / 128;          // 391 tile-rows
    const int WARP_BLKS = (NN * 32 + 255) / 256;

    // feature projections (tensor cores, tf32, cp.async pipelined)
    gemm_tc<false, false><<<GB, 256>>>(img_h, W_img, nullptr, imgf, NN, 2048);
    gemm_tc<false, false><<<GB, 256>>>(txt_h, W_txt, nullptr, txtf, NN, 768);

    // img gate path
    gemm_tc_cat<0><<<GB, 256>>>(emb, imgf, node_id, img_W1, img_b1, h1, NN);
    gemm_tc<true, true><<<GB, 256>>>(h1, img_W2, img_b2, h2, NN, 128);
    gate_fin_kernel<<<WARP_BLKS, 256>>>(h2, img_W3, img_b3, imgf, emb, node_id, imgv);

    // txt gate path
    gemm_tc_cat<0><<<GB, 256>>>(emb, txtf, node_id, txt_W1, txt_b1, h1, NN);
    gemm_tc<true, true><<<GB, 256>>>(h1, txt_W2, txt_b2, h2, NN, 128);
    gate_fin_kernel<<<WARP_BLKS, 256>>>(h2, txt_W3, txt_b3, txtf, emb, node_id, txtv);

    // combine + fc
    gemm_tc_cat<1><<<GB, 256>>>(imgv, txtv, nullptr, comb_W, comb_b, hb, NN);
    gemm_tc<false, false><<<GB, 256>>>(hb, fc_W, nullptr, zb, NN, 128);

    // attention scalars
    attn_e_kernel<<<WARP_BLKS, 256>>>(zb, attn_a, es, ed);

    // edge softmax + aggregate
    init_kernel<<<(NN * HID + 255) / 256, 256>>>(out);
    edge1_kernel<<<(NE + 255) / 256, 256>>>(src, dst);
    edge2_kernel<<<(NE * 32 + 255) / 256, 256>>>(src, dst, out);
    norm_kernel<<<(NN * HID + 255) / 256, 256>>>(out);
}

// round 10
// speedup vs baseline: 3.0708x; 1.0252x over previous
#include <cuda_runtime.h>
#include <cstdint>

#define NN 50000
#define NE 800000
#define HID 128

// ---------------- scratch (static device arrays; no allocation) ----------------
__device__ float g_img_f[(size_t)NN * HID];
__device__ float g_txt_f[(size_t)NN * HID];
__device__ float g_h1   [(size_t)NN * HID];
__device__ float g_h2   [(size_t)NN * HID];
__device__ float g_img_v[(size_t)NN * HID];
__device__ float g_txt_v[(size_t)NN * HID];
__device__ float g_hbuf [(size_t)NN * HID];
__device__ float g_z    [(size_t)NN * HID];
__device__ float g_esrc [NN];
__device__ float g_edst [NN];
// CSR edge machinery
__device__ int   g_cnt  [NN];
__device__ int   g_start[NN];
__device__ int   g_cur  [NN];
__device__ int   g_srcs [NE];
__device__ float g_es_s [NE];

// ---------------------------------------------------------------------------
// tf32 / cp.async helpers
// ---------------------------------------------------------------------------
__device__ __forceinline__ uint32_t f2tf(float f) {
    uint32_t r;
    asm("cvt.rna.tf32.f32 %0, %1;" : "=r"(r) : "f"(f));
    return r;
}

__device__ __forceinline__ void mma_tf32(float* c,
                                         uint32_t a0, uint32_t a1, uint32_t a2, uint32_t a3,
                                         uint32_t b0, uint32_t b1)
{
    asm volatile(
        "mma.sync.aligned.m16n8k8.row.col.f32.tf32.tf32.f32 "
        "{%0,%1,%2,%3},{%4,%5,%6,%7},{%8,%9},{%0,%1,%2,%3};"
        : "+f"(c[0]), "+f"(c[1]), "+f"(c[2]), "+f"(c[3])
        : "r"(a0), "r"(a1), "r"(a2), "r"(a3), "r"(b0), "r"(b1));
}

__device__ __forceinline__ void cp16(uint32_t sdst, const void* gsrc, int predsz) {
    asm volatile("cp.async.cg.shared.global [%0], [%1], 16, %2;"
                 :: "r"(sdst), "l"(gsrc), "r"(predsz));
}
#define CP_COMMIT() asm volatile("cp.async.commit_group;")

// SMEM strides: As[m][20] -> bank (20g+c)%32 permutation; Bs[k][136] -> (8c+g)%32 perm.
#define ASTR 20
#define BSTR 136
#define NSTAGE 4
#define A_TILE_BYTES (128 * ASTR * 4)
#define B_TILE_BYTES (16 * BSTR * 4)
#define GEMM_SMEM (NSTAGE * (A_TILE_BYTES + B_TILE_BYTES))   // 75776 B

// ---------------------------------------------------------------------------
// tensor-core SGEMM (tf32, 4-stage cp.async ring, single sync per k-tile):
// C[M x 128] = act(A[M x K] @ B[K x 128] (+bias)), K % 16 == 0, K/16 >= 3
// block tile 128x128, BK=16, 256 threads = 8 warps (2x4), warp tile 64x32
// ---------------------------------------------------------------------------
template<bool BIAS, bool RELU>
__global__ __launch_bounds__(256, 2)
void gemm_tc(const float* __restrict__ A, const float* __restrict__ B,
             const float* __restrict__ bias, float* __restrict__ C,
             int M, int K)
{
    extern __shared__ char smem_raw[];
    float (*As)[128][ASTR] = (float(*)[128][ASTR])smem_raw;
    float (*Bs)[16][BSTR]  = (float(*)[16][BSTR])(smem_raw + NSTAGE * A_TILE_BYTES);

    const int tid  = threadIdx.x;
    const int warp = tid >> 5;
    const int lane = tid & 31;
    const int m0   = blockIdx.x * 128;

    const int wmb = (warp & 1) * 64;   // warp M offset
    const int wnb = (warp >> 1) * 32;  // warp N offset

    const int ar0 = tid >> 2;          // A row 0..63 (+64 second chunk)
    const int ac0 = (tid & 3) << 2;    // A col group
    const int bn0 = (tid & 31) << 2;   // B n

    float acc[4][4][4];
#pragma unroll
    for (int i = 0; i < 4; i++)
#pragma unroll
        for (int j = 0; j < 4; j++)
#pragma unroll
            for (int v = 0; v < 4; v++) acc[i][j][v] = 0.f;

    auto load_tile = [&](int s, int k0) {
#pragma unroll
        for (int p = 0; p < 2; p++) {
            int row = ar0 + p * 64;
            int gr  = m0 + row;
            cp16((uint32_t)__cvta_generic_to_shared(&As[s][row][ac0]),
                 A + (size_t)gr * K + k0 + ac0, gr < M ? 16 : 0);
        }
#pragma unroll
        for (int p = 0; p < 2; p++) {
            int k = warp + p * 8;
            cp16((uint32_t)__cvta_generic_to_shared(&Bs[s][k][bn0]),
                 B + (size_t)(k0 + k) * HID + bn0, 16);
        }
    };

    const int T = K >> 4;
    load_tile(0, 0);  CP_COMMIT();
    load_tile(1, 16); CP_COMMIT();
    load_tile(2, 32); CP_COMMIT();

    for (int t = 0; t < T; t++) {
        if (t < T - 2)      asm volatile("cp.async.wait_group 2;");
        else if (t == T - 2) asm volatile("cp.async.wait_group 1;");
        else                 asm volatile("cp.async.wait_group 0;");
        __syncthreads();

        if (t + 3 < T) {                 // slot (t+3)%4 == slot of tile t-1 (safe past sync)
            load_tile((t + 3) & 3, (t + 3) << 4);
            CP_COMMIT();
        }

        const int buf = t & 3;
#pragma unroll
        for (int ks = 0; ks < 2; ks++) {
            const int kc = ks * 8 + (lane & 3);
            const int gm = lane >> 2;
            uint32_t af[4][4], bf[4][2];
#pragma unroll
            for (int mt = 0; mt < 4; mt++) {
                int m = wmb + mt * 16 + gm;
                af[mt][0] = f2tf(As[buf][m    ][kc    ]);
                af[mt][1] = f2tf(As[buf][m + 8][kc    ]);
                af[mt][2] = f2tf(As[buf][m    ][kc + 4]);
                af[mt][3] = f2tf(As[buf][m + 8][kc + 4]);
            }
#pragma unroll
            for (int nt = 0; nt < 4; nt++) {
                int n = wnb + nt * 8 + gm;
                bf[nt][0] = f2tf(Bs[buf][kc    ][n]);
                bf[nt][1] = f2tf(Bs[buf][kc + 4][n]);
            }
#pragma unroll
            for (int mt = 0; mt < 4; mt++)
#pragma unroll
                for (int nt = 0; nt < 4; nt++)
                    mma_tf32(acc[mt][nt], af[mt][0], af[mt][1], af[mt][2], af[mt][3],
                             bf[nt][0], bf[nt][1]);
        }
    }

    // ---- epilogue ----
#pragma unroll
    for (int mt = 0; mt < 4; mt++) {
        int r0 = m0 + wmb + mt * 16 + (lane >> 2);
#pragma unroll
        for (int nt = 0; nt < 4; nt++) {
            int c = wnb + nt * 8 + ((lane & 3) << 1);
            float bb0 = 0.f, bb1 = 0.f;
            if (BIAS) { bb0 = bias[c]; bb1 = bias[c + 1]; }
            float v0 = acc[mt][nt][0] + bb0, v1 = acc[mt][nt][1] + bb1;
            float v2 = acc[mt][nt][2] + bb0, v3 = acc[mt][nt][3] + bb1;
            if (RELU) {
                v0 = fmaxf(v0, 0.f); v1 = fmaxf(v1, 0.f);
                v2 = fmaxf(v2, 0.f); v3 = fmaxf(v3, 0.f);
            }
            if (r0 < M)     *(float2*)(C + (size_t)r0 * HID + c)       = make_float2(v0, v1);
            if (r0 + 8 < M) *(float2*)(C + (size_t)(r0 + 8) * HID + c) = make_float2(v2, v3);
        }
    }
}

// ---------------------------------------------------------------------------
// tensor-core concat SGEMM (4-stage ring):
// A row r = [ P[gidx?gidx[r]:r] (128) | Q[r] (128) ], K = 256
// MODE 0: C = relu(A@B + bias)                        (gate MLP layer 1)
// MODE 1: gate = A@B + bias; C = gate*P + (1-gate)*Q  (comb combine, no gather)
// ---------------------------------------------------------------------------
template<int MODE>
__global__ __launch_bounds__(256, 2)
void gemm_tc_cat(const float* __restrict__ P, const float* __restrict__ Q,
                 const int* __restrict__ gidx,
                 const float* __restrict__ B, const float* __restrict__ bias,
                 float* __restrict__ C, int M)
{
    extern __shared__ char smem_raw[];
    float (*As)[128][ASTR] = (float(*)[128][ASTR])smem_raw;
    float (*Bs)[16][BSTR]  = (float(*)[16][BSTR])(smem_raw + NSTAGE * A_TILE_BYTES);

    const int tid  = threadIdx.x;
    const int warp = tid >> 5;
    const int lane = tid & 31;
    const int m0   = blockIdx.x * 128;

    const int wmb = (warp & 1) * 64;
    const int wnb = (warp >> 1) * 32;

    const int ar0 = tid >> 2;
    const int ac0 = (tid & 3) << 2;
    const int bn0 = (tid & 31) << 2;

    int grow[2], rgat[2], pr[2];
#pragma unroll
    for (int p = 0; p < 2; p++) {
        int row = ar0 + p * 64;
        int gr  = m0 + row;
        grow[p] = gr;
        pr[p]   = (gr < M) ? 16 : 0;
        rgat[p] = (MODE == 0) ? ((gr < M) ? gidx[gr] : 0) : gr;
    }

    float acc[4][4][4];
#pragma unroll
    for (int i = 0; i < 4; i++)
#pragma unroll
        for (int j = 0; j < 4; j++)
#pragma unroll
            for (int v = 0; v < 4; v++) acc[i][j][v] = 0.f;

    auto load_tile = [&](int s, int k0) {
        const float* S  = (k0 < 128) ? P : Q;
        const int cbase = (k0 < 128) ? k0 : (k0 - 128);
        const bool gath = (k0 < 128);
#pragma unroll
        for (int p = 0; p < 2; p++) {
            int row = ar0 + p * 64;
            int rr  = gath ? rgat[p] : grow[p];
            cp16((uint32_t)__cvta_generic_to_shared(&As[s][row][ac0]),
                 S + (size_t)rr * HID + cbase + ac0, pr[p]);
        }
#pragma unroll
        for (int p = 0; p < 2; p++) {
            int k = warp + p * 8;
            cp16((uint32_t)__cvta_generic_to_shared(&Bs[s][k][bn0]),
                 B + (size_t)(k0 + k) * HID + bn0, 16);
        }
    };

    const int T = 16;  // K = 256
    load_tile(0, 0);  CP_COMMIT();
    load_tile(1, 16); CP_COMMIT();
    load_tile(2, 32); CP_COMMIT();

    for (int t = 0; t < T; t++) {
        if (t < T - 2)      asm volatile("cp.async.wait_group 2;");
        else if (t == T - 2) asm volatile("cp.async.wait_group 1;");
        else                 asm volatile("cp.async.wait_group 0;");
        __syncthreads();

        if (t + 3 < T) {
            load_tile((t + 3) & 3, (t + 3) << 4);
            CP_COMMIT();
        }

        const int buf = t & 3;
#pragma unroll
        for (int ks = 0; ks < 2; ks++) {
            const int kc = ks * 8 + (lane & 3);
            const int gm = lane >> 2;
            uint32_t af[4][4], bf[4][2];
#pragma unroll
            for (int mt = 0; mt < 4; mt++) {
                int m = wmb + mt * 16 + gm;
                af[mt][0] = f2tf(As[buf][m    ][kc    ]);
                af[mt][1] = f2tf(As[buf][m + 8][kc    ]);
                af[mt][2] = f2tf(As[buf][m    ][kc + 4]);
                af[mt][3] = f2tf(As[buf][m + 8][kc + 4]);
            }
#pragma unroll
            for (int nt = 0; nt < 4; nt++) {
                int n = wnb + nt * 8 + gm;
                bf[nt][0] = f2tf(Bs[buf][kc    ][n]);
                bf[nt][1] = f2tf(Bs[buf][kc + 4][n]);
            }
#pragma unroll
            for (int mt = 0; mt < 4; mt++)
#pragma unroll
                for (int nt = 0; nt < 4; nt++)
                    mma_tf32(acc[mt][nt], af[mt][0], af[mt][1], af[mt][2], af[mt][3],
                             bf[nt][0], bf[nt][1]);
        }
    }

#pragma unroll
    for (int mt = 0; mt < 4; mt++) {
        int r0 = m0 + wmb + mt * 16 + (lane >> 2);
#pragma unroll
        for (int nt = 0; nt < 4; nt++) {
            int c = wnb + nt * 8 + ((lane & 3) << 1);
            float bb0 = bias[c], bb1 = bias[c + 1];
            float v0 = acc[mt][nt][0] + bb0, v1 = acc[mt][nt][1] + bb1;
            float v2 = acc[mt][nt][2] + bb0, v3 = acc[mt][nt][3] + bb1;
#pragma unroll
            for (int h = 0; h < 2; h++) {
                int r = r0 + h * 8;
                if (r >= M) continue;
                float g0 = h ? v2 : v0, g1 = h ? v3 : v1;
                float o0, o1;
                if (MODE == 0) {
                    o0 = fmaxf(g0, 0.f);
                    o1 = fmaxf(g1, 0.f);
                } else {
                    float2 pv = *(const float2*)(P + (size_t)r * HID + c);
                    float2 qv = *(const float2*)(Q + (size_t)r * HID + c);
                    o0 = g0 * pv.x + (1.f - g0) * qv.x;
                    o1 = g1 * pv.y + (1.f - g1) * qv.y;
                }
                *(float2*)(C + (size_t)r * HID + c) = make_float2(o0, o1);
            }
        }
    }
}

// ---------------------------------------------------------------------------
// gate finalize: g = sigmoid(h2 . W3 + b3); v = g*f + (1-g)*emb[nid]
// ---------------------------------------------------------------------------
__global__ void gate_fin_kernel(const float* __restrict__ h2,
                                const float* __restrict__ W3,
                                const float* __restrict__ b3,
                                const float* __restrict__ f,
                                const float* __restrict__ emb,
                                const int* __restrict__ nid,
                                float* __restrict__ v_out)
{
    int w = (blockIdx.x * blockDim.x + threadIdx.x) >> 5;
    int lane = threadIdx.x & 31;
    if (w >= NN) return;
    float4 h4 = *(const float4*)(h2 + (size_t)w * HID + lane * 4);
    float4 w4 = *(const float4*)(W3 + lane * 4);
    float d = h4.x * w4.x + h4.y * w4.y + h4.z * w4.z + h4.w * w4.w;
#pragma unroll
    for (int o = 16; o; o >>= 1) d += __shfl_xor_sync(0xffffffffu, d, o);
    float g = 1.f / (1.f + expf(-(d + b3[0])));
    int e = nid[w];
    float4 fv = *(const float4*)(f + (size_t)w * HID + lane * 4);
    float4 ev = *(const float4*)(emb + (size_t)e * HID + lane * 4);
    float4 o4;
    o4.x = g * fv.x + (1.f - g) * ev.x;
    o4.y = g * fv.y + (1.f - g) * ev.y;
    o4.z = g * fv.z + (1.f - g) * ev.z;
    o4.w = g * fv.w + (1.f - g) * ev.w;
    *(float4*)(v_out + (size_t)w * HID + lane * 4) = o4;
}

// e_src = z . a1, e_dst = z . a2  (one warp per node)
__global__ void attn_e_kernel(const float* __restrict__ z,
                              const float* __restrict__ a,
                              float* __restrict__ es, float* __restrict__ ed)
{
    int w = (blockIdx.x * blockDim.x + threadIdx.x) >> 5;
    int lane = threadIdx.x & 31;
    if (w >= NN) return;
    float4 zv = *(const float4*)(z + (size_t)w * HID + lane * 4);
    float4 a1 = *(const float4*)(a + lane * 4);
    float4 a2 = *(const float4*)(a + HID + lane * 4);
    float d1 = zv.x * a1.x + zv.y * a1.y + zv.z * a1.z + zv.w * a1.w;
    float d2 = zv.x * a2.x + zv.y * a2.y + zv.z * a2.z + zv.w * a2.w;
#pragma unroll
    for (int o = 16; o; o >>= 1) {
        d1 += __shfl_xor_sync(0xffffffffu, d1, o);
        d2 += __shfl_xor_sync(0xffffffffu, d2, o);
    }
    if (lane == 0) { es[w] = d1; ed[w] = d2; }
}

// ---------------------------------------------------------------------------
// Edge phase: build CSR by dst, then warp-per-dst softmax aggregate (no atomics
// on the 25.6M-element output).
// ---------------------------------------------------------------------------
__global__ void zero_cnt_kernel()
{
    int i = blockIdx.x * blockDim.x + threadIdx.x;
    if (i < NN) { g_cnt[i] = 0; g_cur[i] = 0; }
}

__global__ void hist_kernel(const int* __restrict__ dst)
{
    int e = blockIdx.x * blockDim.x + threadIdx.x;
    if (e < NE) atomicAdd(&g_cnt[dst[e]], 1);
}

// single-block exclusive scan over g_cnt -> g_start (1024 threads)
__global__ void scan_kernel()
{
    __shared__ int warp_sums[32];
    __shared__ int s_carry;
    int tid = threadIdx.x, lane = tid & 31, wid = tid >> 5;
    if (tid == 0) s_carry = 0;
    __syncthreads();
    for (int base = 0; base < NN; base += 1024) {
        int i = base + tid;
        int v = (i < NN) ? g_cnt[i] : 0;
        int x = v;
#pragma unroll
        for (int o = 1; o < 32; o <<= 1) {
            int y = __shfl_up_sync(0xffffffffu, x, o);
            if (lane >= o) x += y;
        }
        if (lane == 31) warp_sums[wid] = x;
        __syncthreads();
        if (wid == 0) {
            int ws = warp_sums[lane];
#pragma unroll
            for (int o = 1; o < 32; o <<= 1) {
                int y = __shfl_up_sync(0xffffffffu, ws, o);
                if (lane >= o) ws += y;
            }
            warp_sums[lane] = ws;
        }
        __syncthreads();
        int incl = x + (wid ? warp_sums[wid - 1] : 0);
        int carry = s_carry;
        if (i < NN) g_start[i] = carry + incl - v;
        __syncthreads();
        if (tid == 0) s_carry = carry + warp_sums[31];
        __syncthreads();
    }
}

// scatter edges into dst-sorted order, computing e = leaky(es[src]+ed[dst])
__global__ void scatter_kernel(const int* __restrict__ src, const int* __restrict__ dst)
{
    int e = blockIdx.x * blockDim.x + threadIdx.x;
    if (e >= NE) return;
    int s = src[e], d = dst[e];
    float v = g_esrc[s] + g_edst[d];
    v = (v > 0.f) ? v : 0.01f * v;
    int pos = atomicAdd(&g_cur[d], 1);
    int idx = g_start[d] + pos;
    g_srcs[idx] = s;
    g_es_s[idx] = v;
}

// warp per dst node: softmax over its edge segment + weighted z gather
__global__ __launch_bounds__(256)
void aggregate_kernel(float* __restrict__ out)
{
    __shared__ float ws[8][32];
    __shared__ int   ss[8][32];
    int w    = (blockIdx.x * blockDim.x + threadIdx.x) >> 5;
    int lane = threadIdx.x & 31;
    int wib  = (threadIdx.x >> 5);
    if (w >= NN) return;

    int s0  = g_start[w];
    int deg = g_cnt[w];

    // segment max
    float mx = -3.402823466e38f;
    for (int j = lane; j < deg; j += 32) mx = fmaxf(mx, g_es_s[s0 + j]);
#pragma unroll
    for (int o = 16; o; o >>= 1) mx = fmaxf(mx, __shfl_xor_sync(0xffffffffu, mx, o));

    // denominator
    float dsum = 0.f;
    for (int j = lane; j < deg; j += 32) dsum += expf(g_es_s[s0 + j] - mx);
#pragma unroll
    for (int o = 16; o; o >>= 1) dsum += __shfl_xor_sync(0xffffffffu, dsum, o);
    float inv = 1.f / fmaxf(dsum, 1e-20f);

    // weighted aggregation: each lane owns 4 output columns
    float4 acc = make_float4(0.f, 0.f, 0.f, 0.f);
    for (int base = 0; base < deg; base += 32) {
        int j = base + lane;
        float wv = 0.f; int sj = 0;
        if (j < deg) {
            wv = expf(g_es_s[s0 + j] - mx) * inv;
            sj = g_srcs[s0 + j];
        }
        ws[wib][lane] = wv;
        ss[wib][lane] = sj;
        __syncwarp();
        int lim = min(32, deg - base);
        for (int jj = 0; jj < lim; jj++) {
            float wj = ws[wib][jj];
            const float4 zv = *(const float4*)(g_z + (size_t)ss[wib][jj] * HID + lane * 4);
            acc.x += wj * zv.x; acc.y += wj * zv.y;
            acc.z += wj * zv.z; acc.w += wj * zv.w;
        }
        __syncwarp();
    }
    *(float4*)(out + (size_t)w * HID + lane * 4) = acc;
}

// ---------------------------------------------------------------------------
extern "C" void kernel_launch(void* const* d_in, const int* in_sizes, int n_in,
                              void* d_out, int out_size)
{
    const int*   node_id = (const int*)  d_in[0];
    const float* img_h   = (const float*)d_in[1];
    const float* txt_h   = (const float*)d_in[2];
    const int*   src     = (const int*)  d_in[3];
    const int*   dst     = (const int*)  d_in[4];
    const float* emb     = (const float*)d_in[5];
    const float* W_img   = (const float*)d_in[6];
    const float* img_W1  = (const float*)d_in[7];
    const float* img_b1  = (const float*)d_in[8];
    const float* img_W2  = (const float*)d_in[9];
    const float* img_b2  = (const float*)d_in[10];
    const float* img_W3  = (const float*)d_in[11];
    const float* img_b3  = (const float*)d_in[12];
    const float* W_txt   = (const float*)d_in[13];
    const float* txt_W1  = (const float*)d_in[14];
    const float* txt_b1  = (const float*)d_in[15];
    const float* txt_W2  = (const float*)d_in[16];
    const float* txt_b2  = (const float*)d_in[17];
    const float* txt_W3  = (const float*)d_in[18];
    const float* txt_b3  = (const float*)d_in[19];
    const float* comb_W  = (const float*)d_in[20];
    const float* comb_b  = (const float*)d_in[21];
    const float* fc_W    = (const float*)d_in[22];
    const float* attn_a  = (const float*)d_in[23];
    float* out = (float*)d_out;

    float *imgf, *txtf, *h1, *h2, *imgv, *txtv, *hb, *zb, *es, *ed;
    cudaGetSymbolAddress((void**)&imgf, g_img_f);
    cudaGetSymbolAddress((void**)&txtf, g_txt_f);
    cudaGetSymbolAddress((void**)&h1,   g_h1);
    cudaGetSymbolAddress((void**)&h2,   g_h2);
    cudaGetSymbolAddress((void**)&imgv, g_img_v);
    cudaGetSymbolAddress((void**)&txtv, g_txt_v);
    cudaGetSymbolAddress((void**)&hb,   g_hbuf);
    cudaGetSymbolAddress((void**)&zb,   g_z);
    cudaGetSymbolAddress((void**)&es,   g_esrc);
    cudaGetSymbolAddress((void**)&ed,   g_edst);

    // dynamic SMEM opt-in (idempotent; host-side, not a stream op)
    cudaFuncSetAttribute(gemm_tc<false, false>, cudaFuncAttributeMaxDynamicSharedMemorySize, GEMM_SMEM);
    cudaFuncSetAttribute(gemm_tc<true,  true >, cudaFuncAttributeMaxDynamicSharedMemorySize, GEMM_SMEM);
    cudaFuncSetAttribute(gemm_tc_cat<0>,        cudaFuncAttributeMaxDynamicSharedMemorySize, GEMM_SMEM);
    cudaFuncSetAttribute(gemm_tc_cat<1>,        cudaFuncAttributeMaxDynamicSharedMemorySize, GEMM_SMEM);

    const int GB = (NN + 127) / 128;          // 391 tile-rows
    const int WARP_BLKS = (NN * 32 + 255) / 256;

    // feature projections (tf32 tensor cores, 4-stage cp.async ring)
    gemm_tc<false, false><<<GB, 256, GEMM_SMEM>>>(img_h, W_img, nullptr, imgf, NN, 2048);
    gemm_tc<false, false><<<GB, 256, GEMM_SMEM>>>(txt_h, W_txt, nullptr, txtf, NN, 768);

    // img gate path
    gemm_tc_cat<0><<<GB, 256, GEMM_SMEM>>>(emb, imgf, node_id, img_W1, img_b1, h1, NN);
    gemm_tc<true, true><<<GB, 256, GEMM_SMEM>>>(h1, img_W2, img_b2, h2, NN, 128);
    gate_fin_kernel<<<WARP_BLKS, 256>>>(h2, img_W3, img_b3, imgf, emb, node_id, imgv);

    // txt gate path
    gemm_tc_cat<0><<<GB, 256, GEMM_SMEM>>>(emb, txtf, node_id, txt_W1, txt_b1, h1, NN);
    gemm_tc<true, true><<<GB, 256, GEMM_SMEM>>>(h1, txt_W2, txt_b2, h2, NN, 128);
    gate_fin_kernel<<<WARP_BLKS, 256>>>(h2, txt_W3, txt_b3, txtf, emb, node_id, txtv);

    // combine + fc
    gemm_tc_cat<1><<<GB, 256, GEMM_SMEM>>>(imgv, txtv, nullptr, comb_W, comb_b, hb, NN);
    gemm_tc<false, false><<<GB, 256, GEMM_SMEM>>>(hb, fc_W, nullptr, zb, NN, 128);

    // attention scalars
    attn_e_kernel<<<WARP_BLKS, 256>>>(zb, attn_a, es, ed);

    // edge softmax + aggregate via CSR (no output atomics)
    zero_cnt_kernel<<<(NN + 255) / 256, 256>>>();
    hist_kernel<<<(NE + 255) / 256, 256>>>(dst);
    scan_kernel<<<1, 1024>>>();
    scatter_kernel<<<(NE + 255) / 256, 256>>>(src, dst);
    aggregate_kernel<<<(NN * 32 + 255) / 256, 256>>>(out);
}

// round 13
// speedup vs baseline: 3.4433x; 1.1213x over previous
#include <cuda_runtime.h>
#include <cstdint>

#define NN 50000
#define NE 800000
#define HID 128

// ---------------- scratch (static device arrays; no allocation) ----------------
__device__ float g_img_f[(size_t)NN * HID];
__device__ float g_txt_f[(size_t)NN * HID];
__device__ float g_h1a  [(size_t)NN * HID];
__device__ float g_h1b  [(size_t)NN * HID];
__device__ float g_h2a  [(size_t)NN * HID];
__device__ float g_h2b  [(size_t)NN * HID];
__device__ float g_img_v[(size_t)NN * HID];
__device__ float g_txt_v[(size_t)NN * HID];
__device__ float g_hbuf [(size_t)NN * HID];
__device__ float g_z    [(size_t)NN * HID];
__device__ float g_esrc [NN];
__device__ float g_edst [NN];
// CSR edge machinery
__device__ int   g_cnt  [NN];
__device__ int   g_start[NN];
__device__ int   g_cur  [NN];
__device__ int   g_srcs [NE];
__device__ float g_es_s [NE];
// tf32-preconverted weights (concatenated)
#define OFF_WIMG  0
#define OFF_WTXT  262144
#define OFF_IW1   360448
#define OFF_IW2   393216
#define OFF_TW1   409600
#define OFF_TW2   442368
#define OFF_CW    458752
#define OFF_FW    491520
#define WTF_TOTAL 507904
__device__ float g_wtf[WTF_TOTAL];

// ---------------------------------------------------------------------------
// tf32 / cp.async helpers
// ---------------------------------------------------------------------------
__device__ __forceinline__ uint32_t f2tf(float f) {
    uint32_t r;
    asm("cvt.rna.tf32.f32 %0, %1;" : "=r"(r) : "f"(f));
    return r;
}

__device__ __forceinline__ void mma_tf32(float* c,
                                         uint32_t a0, uint32_t a1, uint32_t a2, uint32_t a3,
                                         uint32_t b0, uint32_t b1)
{
    asm volatile(
        "mma.sync.aligned.m16n8k8.row.col.f32.tf32.tf32.f32 "
        "{%0,%1,%2,%3},{%4,%5,%6,%7},{%8,%9},{%0,%1,%2,%3};"
        : "+f"(c[0]), "+f"(c[1]), "+f"(c[2]), "+f"(c[3])
        : "r"(a0), "r"(a1), "r"(a2), "r"(a3), "r"(b0), "r"(b1));
}

__device__ __forceinline__ void cp16(uint32_t sdst, const void* gsrc, int predsz) {
    asm volatile("cp.async.cg.shared.global [%0], [%1], 16, %2;"
                 :: "r"(sdst), "l"(gsrc), "r"(predsz));
}
#define CP_COMMIT() asm volatile("cp.async.commit_group;")

// SMEM strides: As[m][20] -> bank (20g+c)%32 permutation; Bs[k][136] -> (8c+g)%32 perm.
#define ASTR 20
#define BSTR 136
#define NSTAGE 4
#define A_TILE_BYTES (128 * ASTR * 4)
#define B_TILE_BYTES (16 * BSTR * 4)
#define GEMM_SMEM (NSTAGE * (A_TILE_BYTES + B_TILE_BYTES))   // 75776 B

// weight tf32 pre-convert: one pass over all B matrices
__global__ void wconv_kernel(const float* __restrict__ W_img, const float* __restrict__ W_txt,
                             const float* __restrict__ iW1,   const float* __restrict__ iW2,
                             const float* __restrict__ tW1,   const float* __restrict__ tW2,
                             const float* __restrict__ cW,    const float* __restrict__ fW)
{
    int i = blockIdx.x * blockDim.x + threadIdx.x;
    float v;
    if      (i < OFF_WTXT) v = W_img[i - OFF_WIMG];
    else if (i < OFF_IW1)  v = W_txt[i - OFF_WTXT];
    else if (i < OFF_IW2)  v = iW1[i - OFF_IW1];
    else if (i < OFF_TW1)  v = iW2[i - OFF_IW2];
    else if (i < OFF_TW2)  v = tW1[i - OFF_TW1];
    else if (i < OFF_CW)   v = tW2[i - OFF_TW2];
    else if (i < OFF_FW)   v = cW[i - OFF_CW];
    else if (i < WTF_TOTAL) v = fW[i - OFF_FW];
    else return;
    g_wtf[i] = __uint_as_float(f2tf(v));
}

// ---------------------------------------------------------------------------
// tensor-core SGEMM (tf32, 4-stage cp.async ring, B pre-rounded to tf32):
// C[M x 128] = act(A[M x K] @ B[K x 128] (+bias)), K % 16 == 0, K/16 >= 3
// block 128x128, BK=16, 8 warps in 4(M)x2(N), warp tile 32x64
// DUAL: blockIdx.y selects parameter set (merged independent launches)
// ---------------------------------------------------------------------------
template<bool BIAS, bool RELU, bool DUAL>
__global__ __launch_bounds__(256, 2)
void gemm_tc(const float* __restrict__ A0, const float* __restrict__ B0,
             const float* __restrict__ bias0, float* __restrict__ C0, int M, int K0,
             const float* A1, const float* B1, const float* bias1, float* C1, int K1)
{
    extern __shared__ char smem_raw[];
    float (*As)[128][ASTR] = (float(*)[128][ASTR])smem_raw;
    float (*Bs)[16][BSTR]  = (float(*)[16][BSTR])(smem_raw + NSTAGE * A_TILE_BYTES);

    const bool alt = DUAL && (blockIdx.y != 0);
    const float* A    = alt ? A1 : A0;
    const float* B    = alt ? B1 : B0;
    const float* bias = alt ? bias1 : bias0;
    float* C          = alt ? C1 : C0;
    const int K       = alt ? K1 : K0;

    const int tid  = threadIdx.x;
    const int warp = tid >> 5;
    const int lane = tid & 31;
    const int m0   = blockIdx.x * 128;

    const int wmb = (warp & 3) * 32;   // warp M offset (4 groups)
    const int wnb = (warp >> 2) * 64;  // warp N offset (2 groups)

    const int ar0 = tid >> 2;          // A row 0..63 (+64 second chunk)
    const int ac0 = (tid & 3) << 2;    // A col group
    const int bn0 = (tid & 31) << 2;   // B n

    float acc[2][8][4];
#pragma unroll
    for (int i = 0; i < 2; i++)
#pragma unroll
        for (int j = 0; j < 8; j++)
#pragma unroll
            for (int v = 0; v < 4; v++) acc[i][j][v] = 0.f;

    auto load_tile = [&](int s, int k0) {
#pragma unroll
        for (int p = 0; p < 2; p++) {
            int row = ar0 + p * 64;
            int gr  = m0 + row;
            cp16((uint32_t)__cvta_generic_to_shared(&As[s][row][ac0]),
                 A + (size_t)gr * K + k0 + ac0, gr < M ? 16 : 0);
        }
#pragma unroll
        for (int p = 0; p < 2; p++) {
            int k = warp + p * 8;
            cp16((uint32_t)__cvta_generic_to_shared(&Bs[s][k][bn0]),
                 B + (size_t)(k0 + k) * HID + bn0, 16);
        }
    };

    const int T = K >> 4;
    load_tile(0, 0);  CP_COMMIT();
    load_tile(1, 16); CP_COMMIT();
    load_tile(2, 32); CP_COMMIT();

    for (int t = 0; t < T; t++) {
        if (t < T - 2)       asm volatile("cp.async.wait_group 2;");
        else if (t == T - 2) asm volatile("cp.async.wait_group 1;");
        else                 asm volatile("cp.async.wait_group 0;");
        __syncthreads();

        if (t + 3 < T) {
            load_tile((t + 3) & 3, (t + 3) << 4);
            CP_COMMIT();
        }

        const int buf = t & 3;
#pragma unroll
        for (int ks = 0; ks < 2; ks++) {
            const int kc = ks * 8 + (lane & 3);
            const int gm = lane >> 2;
            uint32_t af[2][4], bf[8][2];
#pragma unroll
            for (int mt = 0; mt < 2; mt++) {
                int m = wmb + mt * 16 + gm;
                af[mt][0] = f2tf(As[buf][m    ][kc    ]);
                af[mt][1] = f2tf(As[buf][m + 8][kc    ]);
                af[mt][2] = f2tf(As[buf][m    ][kc + 4]);
                af[mt][3] = f2tf(As[buf][m + 8][kc + 4]);
            }
#pragma unroll
            for (int nt = 0; nt < 8; nt++) {
                int n = wnb + nt * 8 + gm;
                bf[nt][0] = __float_as_uint(Bs[buf][kc    ][n]);   // pre-rounded tf32
                bf[nt][1] = __float_as_uint(Bs[buf][kc + 4][n]);
            }
#pragma unroll
            for (int mt = 0; mt < 2; mt++)
#pragma unroll
                for (int nt = 0; nt < 8; nt++)
                    mma_tf32(acc[mt][nt], af[mt][0], af[mt][1], af[mt][2], af[mt][3],
                             bf[nt][0], bf[nt][1]);
        }
    }

    // ---- epilogue ----
#pragma unroll
    for (int mt = 0; mt < 2; mt++) {
        int r0 = m0 + wmb + mt * 16 + (lane >> 2);
#pragma unroll
        for (int nt = 0; nt < 8; nt++) {
            int c = wnb + nt * 8 + ((lane & 3) << 1);
            float bb0 = 0.f, bb1 = 0.f;
            if (BIAS) { bb0 = bias[c]; bb1 = bias[c + 1]; }
            float v0 = acc[mt][nt][0] + bb0, v1 = acc[mt][nt][1] + bb1;
            float v2 = acc[mt][nt][2] + bb0, v3 = acc[mt][nt][3] + bb1;
            if (RELU) {
                v0 = fmaxf(v0, 0.f); v1 = fmaxf(v1, 0.f);
                v2 = fmaxf(v2, 0.f); v3 = fmaxf(v3, 0.f);
            }
            if (r0 < M)     *(float2*)(C + (size_t)r0 * HID + c)       = make_float2(v0, v1);
            if (r0 + 8 < M) *(float2*)(C + (size_t)(r0 + 8) * HID + c) = make_float2(v2, v3);
        }
    }
}

// ---------------------------------------------------------------------------
// tensor-core concat SGEMM: A row r = [ P[gidx?gidx[r]:r] | Q[r] ], K = 256
// MODE 0 (DUAL ok): C = relu(A@B + bias)
// MODE 1: gate = A@B + bias; C = gate*P + (1-gate)*Q
// ---------------------------------------------------------------------------
template<int MODE, bool DUAL>
__global__ __launch_bounds__(256, 2)
void gemm_tc_cat(const float* __restrict__ P,
                 const float* __restrict__ Q0, const int* __restrict__ gidx,
                 const float* __restrict__ B0, const float* __restrict__ bias0,
                 float* __restrict__ C0, int M,
                 const float* Q1, const float* B1, const float* bias1, float* C1)
{
    extern __shared__ char smem_raw[];
    float (*As)[128][ASTR] = (float(*)[128][ASTR])smem_raw;
    float (*Bs)[16][BSTR]  = (float(*)[16][BSTR])(smem_raw + NSTAGE * A_TILE_BYTES);

    const bool alt = DUAL && (blockIdx.y != 0);
    const float* Q    = alt ? Q1 : Q0;
    const float* B    = alt ? B1 : B0;
    const float* bias = alt ? bias1 : bias0;
    float* C          = alt ? C1 : C0;

    const int tid  = threadIdx.x;
    const int warp = tid >> 5;
    const int lane = tid & 31;
    const int m0   = blockIdx.x * 128;

    const int wmb = (warp & 3) * 32;
    const int wnb = (warp >> 2) * 64;

    const int ar0 = tid >> 2;
    const int ac0 = (tid & 3) << 2;
    const int bn0 = (tid & 31) << 2;

    int grow[2], rgat[2], pr[2];
#pragma unroll
    for (int p = 0; p < 2; p++) {
        int row = ar0 + p * 64;
        int gr  = m0 + row;
        grow[p] = gr;
        pr[p]   = (gr < M) ? 16 : 0;
        rgat[p] = (MODE == 0) ? ((gr < M) ? gidx[gr] : 0) : gr;
    }

    float acc[2][8][4];
#pragma unroll
    for (int i = 0; i < 2; i++)
#pragma unroll
        for (int j = 0; j < 8; j++)
#pragma unroll
            for (int v = 0; v < 4; v++) acc[i][j][v] = 0.f;

    auto load_tile = [&](int s, int k0) {
        const float* S  = (k0 < 128) ? P : Q;
        const int cbase = (k0 < 128) ? k0 : (k0 - 128);
        const bool gath = (k0 < 128);
#pragma unroll
        for (int p = 0; p < 2; p++) {
            int row = ar0 + p * 64;
            int rr  = gath ? rgat[p] : grow[p];
            cp16((uint32_t)__cvta_generic_to_shared(&As[s][row][ac0]),
                 S + (size_t)rr * HID + cbase + ac0, pr[p]);
        }
#pragma unroll
        for (int p = 0; p < 2; p++) {
            int k = warp + p * 8;
            cp16((uint32_t)__cvta_generic_to_shared(&Bs[s][k][bn0]),
                 B + (size_t)(k0 + k) * HID + bn0, 16);
        }
    };

    const int T = 16;  // K = 256
    load_tile(0, 0);  CP_COMMIT();
    load_tile(1, 16); CP_COMMIT();
    load_tile(2, 32); CP_COMMIT();

    for (int t = 0; t < T; t++) {
        if (t < T - 2)       asm volatile("cp.async.wait_group 2;");
        else if (t == T - 2) asm volatile("cp.async.wait_group 1;");
        else                 asm volatile("cp.async.wait_group 0;");
        __syncthreads();

        if (t + 3 < T) {
            load_tile((t + 3) & 3, (t + 3) << 4);
            CP_COMMIT();
        }

        const int buf = t & 3;
#pragma unroll
        for (int ks = 0; ks < 2; ks++) {
            const int kc = ks * 8 + (lane & 3);
            const int gm = lane >> 2;
            uint32_t af[2][4], bf[8][2];
#pragma unroll
            for (int mt = 0; mt < 2; mt++) {
                int m = wmb + mt * 16 + gm;
                af[mt][0] = f2tf(As[buf][m    ][kc    ]);
                af[mt][1] = f2tf(As[buf][m + 8][kc    ]);
                af[mt][2] = f2tf(As[buf][m    ][kc + 4]);
                af[mt][3] = f2tf(As[buf][m + 8][kc + 4]);
            }
#pragma unroll
            for (int nt = 0; nt < 8; nt++) {
                int n = wnb + nt * 8 + gm;
                bf[nt][0] = __float_as_uint(Bs[buf][kc    ][n]);
                bf[nt][1] = __float_as_uint(Bs[buf][kc + 4][n]);
            }
#pragma unroll
            for (int mt = 0; mt < 2; mt++)
#pragma unroll
                for (int nt = 0; nt < 8; nt++)
                    mma_tf32(acc[mt][nt], af[mt][0], af[mt][1], af[mt][2], af[mt][3],
                             bf[nt][0], bf[nt][1]);
        }
    }

#pragma unroll
    for (int mt = 0; mt < 2; mt++) {
        int r0 = m0 + wmb + mt * 16 + (lane >> 2);
#pragma unroll
        for (int nt = 0; nt < 8; nt++) {
            int c = wnb + nt * 8 + ((lane & 3) << 1);
            float bb0 = bias[c], bb1 = bias[c + 1];
            float v0 = acc[mt][nt][0] + bb0, v1 = acc[mt][nt][1] + bb1;
            float v2 = acc[mt][nt][2] + bb0, v3 = acc[mt][nt][3] + bb1;
#pragma unroll
            for (int h = 0; h < 2; h++) {
                int r = r0 + h * 8;
                if (r >= M) continue;
                float g0 = h ? v2 : v0, g1 = h ? v3 : v1;
                float o0, o1;
                if (MODE == 0) {
                    o0 = fmaxf(g0, 0.f);
                    o1 = fmaxf(g1, 0.f);
                } else {
                    float2 pv = *(const float2*)(P + (size_t)r * HID + c);
                    float2 qv = *(const float2*)(Q + (size_t)r * HID + c);
                    o0 = g0 * pv.x + (1.f - g0) * qv.x;
                    o1 = g1 * pv.y + (1.f - g1) * qv.y;
                }
                *(float2*)(C + (size_t)r * HID + c) = make_float2(o0, o1);
            }
        }
    }
}

// ---------------------------------------------------------------------------
// gate finalize, dual (img path then txt path): one warp per (set, node)
// ---------------------------------------------------------------------------
__global__ void gate_fin_dual(const float* __restrict__ h2a, const float* __restrict__ h2b,
                              const float* __restrict__ W3a, const float* __restrict__ W3b,
                              const float* __restrict__ b3a, const float* __restrict__ b3b,
                              const float* __restrict__ fa,  const float* __restrict__ fb,
                              const float* __restrict__ emb, const int* __restrict__ nid,
                              float* __restrict__ va, float* __restrict__ vb)
{
    int id = (blockIdx.x * blockDim.x + threadIdx.x) >> 5;
    int lane = threadIdx.x & 31;
    if (id >= 2 * NN) return;
    int set = (id >= NN);
    int w = id - set * NN;
    const float* h2 = set ? h2b : h2a;
    const float* W3 = set ? W3b : W3a;
    const float* b3 = set ? b3b : b3a;
    const float* f  = set ? fb  : fa;
    float* v_out    = set ? vb  : va;

    float4 h4 = *(const float4*)(h2 + (size_t)w * HID + lane * 4);
    float4 w4 = *(const float4*)(W3 + lane * 4);
    float d = h4.x * w4.x + h4.y * w4.y + h4.z * w4.z + h4.w * w4.w;
#pragma unroll
    for (int o = 16; o; o >>= 1) d += __shfl_xor_sync(0xffffffffu, d, o);
    float g = 1.f / (1.f + expf(-(d + b3[0])));
    int e = nid[w];
    float4 fv = *(const float4*)(f + (size_t)w * HID + lane * 4);
    float4 ev = *(const float4*)(emb + (size_t)e * HID + lane * 4);
    float4 o4;
    o4.x = g * fv.x + (1.f - g) * ev.x;
    o4.y = g * fv.y + (1.f - g) * ev.y;
    o4.z = g * fv.z + (1.f - g) * ev.z;
    o4.w = g * fv.w + (1.f - g) * ev.w;
    *(float4*)(v_out + (size_t)w * HID + lane * 4) = o4;
}

// e_src = z . a1, e_dst = z . a2  (one warp per node)
__global__ void attn_e_kernel(const float* __restrict__ z,
                              const float* __restrict__ a,
                              float* __restrict__ es, float* __restrict__ ed)
{
    int w = (blockIdx.x * blockDim.x + threadIdx.x) >> 5;
    int lane = threadIdx.x & 31;
    if (w >= NN) return;
    float4 zv = *(const float4*)(z + (size_t)w * HID + lane * 4);
    float4 a1 = *(const float4*)(a + lane * 4);
    float4 a2 = *(const float4*)(a + HID + lane * 4);
    float d1 = zv.x * a1.x + zv.y * a1.y + zv.z * a1.z + zv.w * a1.w;
    float d2 = zv.x * a2.x + zv.y * a2.y + zv.z * a2.z + zv.w * a2.w;
#pragma unroll
    for (int o = 16; o; o >>= 1) {
        d1 += __shfl_xor_sync(0xffffffffu, d1, o);
        d2 += __shfl_xor_sync(0xffffffffu, d2, o);
    }
    if (lane == 0) { es[w] = d1; ed[w] = d2; }
}

// ---------------------------------------------------------------------------
// Edge phase: CSR by dst, warp-per-dst softmax aggregate (no output atomics)
// ---------------------------------------------------------------------------
__global__ void zero_cnt_kernel()
{
    int i = blockIdx.x * blockDim.x + threadIdx.x;
    if (i < NN) { g_cnt[i] = 0; g_cur[i] = 0; }
}

__global__ void hist_kernel(const int* __restrict__ dst)
{
    int e = blockIdx.x * blockDim.x + threadIdx.x;
    if (e < NE) atomicAdd(&g_cnt[dst[e]], 1);
}

// single-block exclusive scan over g_cnt -> g_start (1024 threads)
__global__ void scan_kernel()
{
    __shared__ int warp_sums[32];
    __shared__ int s_carry;
    int tid = threadIdx.x, lane = tid & 31, wid = tid >> 5;
    if (tid == 0) s_carry = 0;
    __syncthreads();
    for (int base = 0; base < NN; base += 1024) {
        int i = base + tid;
        int v = (i < NN) ? g_cnt[i] : 0;
        int x = v;
#pragma unroll
        for (int o = 1; o < 32; o <<= 1) {
            int y = __shfl_up_sync(0xffffffffu, x, o);
            if (lane >= o) x += y;
        }
        if (lane == 31) warp_sums[wid] = x;
        __syncthreads();
        if (wid == 0) {
            int ws = warp_sums[lane];
#pragma unroll
            for (int o = 1; o < 32; o <<= 1) {
                int y = __shfl_up_sync(0xffffffffu, ws, o);
                if (lane >= o) ws += y;
            }
            warp_sums[lane] = ws;
        }
        __syncthreads();
        int incl = x + (wid ? warp_sums[wid - 1] : 0);
        int carry = s_carry;
        if (i < NN) g_start[i] = carry + incl - v;
        __syncthreads();
        if (tid == 0) s_carry = carry + warp_sums[31];
        __syncthreads();
    }
}

__global__ void scatter_kernel(const int* __restrict__ src, const int* __restrict__ dst)
{
    int e = blockIdx.x * blockDim.x + threadIdx.x;
    if (e >= NE) return;
    int s = src[e], d = dst[e];
    float v = g_esrc[s] + g_edst[d];
    v = (v > 0.f) ? v : 0.01f * v;
    int pos = atomicAdd(&g_cur[d], 1);
    int idx = g_start[d] + pos;
    g_srcs[idx] = s;
    g_es_s[idx] = v;
}

__global__ __launch_bounds__(256)
void aggregate_kernel(float* __restrict__ out)
{
    __shared__ float ws[8][32];
    __shared__ int   ss[8][32];
    int w    = (blockIdx.x * blockDim.x + threadIdx.x) >> 5;
    int lane = threadIdx.x & 31;
    int wib  = (threadIdx.x >> 5);
    if (w >= NN) return;

    int s0  = g_start[w];
    int deg = g_cnt[w];

    float mx = -3.402823466e38f;
    for (int j = lane; j < deg; j += 32) mx = fmaxf(mx, g_es_s[s0 + j]);
#pragma unroll
    for (int o = 16; o; o >>= 1) mx = fmaxf(mx, __shfl_xor_sync(0xffffffffu, mx, o));

    float dsum = 0.f;
    for (int j = lane; j < deg; j += 32) dsum += expf(g_es_s[s0 + j] - mx);
#pragma unroll
    for (int o = 16; o; o >>= 1) dsum += __shfl_xor_sync(0xffffffffu, dsum, o);
    float inv = 1.f / fmaxf(dsum, 1e-20f);

    float4 acc = make_float4(0.f, 0.f, 0.f, 0.f);
    for (int base = 0; base < deg; base += 32) {
        int j = base + lane;
        float wv = 0.f; int sj = 0;
        if (j < deg) {
            wv = expf(g_es_s[s0 + j] - mx) * inv;
            sj = g_srcs[s0 + j];
        }
        ws[wib][lane] = wv;
        ss[wib][lane] = sj;
        __syncwarp();
        int lim = min(32, deg - base);
        for (int jj = 0; jj < lim; jj++) {
            float wj = ws[wib][jj];
            const float4 zv = *(const float4*)(g_z + (size_t)ss[wib][jj] * HID + lane * 4);
            acc.x += wj * zv.x; acc.y += wj * zv.y;
            acc.z += wj * zv.z; acc.w += wj * zv.w;
        }
        __syncwarp();
    }
    *(float4*)(out + (size_t)w * HID + lane * 4) = acc;
}

// ---------------------------------------------------------------------------
extern "C" void kernel_launch(void* const* d_in, const int* in_sizes, int n_in,
                              void* d_out, int out_size)
{
    const int*   node_id = (const int*)  d_in[0];
    const float* img_h   = (const float*)d_in[1];
    const float* txt_h   = (const float*)d_in[2];
    const int*   src     = (const int*)  d_in[3];
    const int*   dst     = (const int*)  d_in[4];
    const float* emb     = (const float*)d_in[5];
    const float* W_img   = (const float*)d_in[6];
    const float* img_W1  = (const float*)d_in[7];
    const float* img_b1  = (const float*)d_in[8];
    const float* img_W2  = (const float*)d_in[9];
    const float* img_b2  = (const float*)d_in[10];
    const float* img_W3  = (const float*)d_in[11];
    const float* img_b3  = (const float*)d_in[12];
    const float* W_txt   = (const float*)d_in[13];
    const float* txt_W1  = (const float*)d_in[14];
    const float* txt_b1  = (const float*)d_in[15];
    const float* txt_W2  = (const float*)d_in[16];
    const float* txt_b2  = (const float*)d_in[17];
    const float* txt_W3  = (const float*)d_in[18];
    const float* txt_b3  = (const float*)d_in[19];
    const float* comb_W  = (const float*)d_in[20];
    const float* comb_b  = (const float*)d_in[21];
    const float* fc_W    = (const float*)d_in[22];
    const float* attn_a  = (const float*)d_in[23];
    float* out = (float*)d_out;

    float *imgf, *txtf, *h1a, *h1b, *h2a, *h2b, *imgv, *txtv, *hb, *zb, *es, *ed, *wtf;
    cudaGetSymbolAddress((void**)&imgf, g_img_f);
    cudaGetSymbolAddress((void**)&txtf, g_txt_f);
    cudaGetSymbolAddress((void**)&h1a,  g_h1a);
    cudaGetSymbolAddress((void**)&h1b,  g_h1b);
    cudaGetSymbolAddress((void**)&h2a,  g_h2a);
    cudaGetSymbolAddress((void**)&h2b,  g_h2b);
    cudaGetSymbolAddress((void**)&imgv, g_img_v);
    cudaGetSymbolAddress((void**)&txtv, g_txt_v);
    cudaGetSymbolAddress((void**)&hb,   g_hbuf);
    cudaGetSymbolAddress((void**)&zb,   g_z);
    cudaGetSymbolAddress((void**)&es,   g_esrc);
    cudaGetSymbolAddress((void**)&ed,   g_edst);
    cudaGetSymbolAddress((void**)&wtf,  g_wtf);

    cudaFuncSetAttribute(gemm_tc<false, false, true >, cudaFuncAttributeMaxDynamicSharedMemorySize, GEMM_SMEM);
    cudaFuncSetAttribute(gemm_tc<true,  true,  true >, cudaFuncAttributeMaxDynamicSharedMemorySize, GEMM_SMEM);
    cudaFuncSetAttribute(gemm_tc<false, false, false>, cudaFuncAttributeMaxDynamicSharedMemorySize, GEMM_SMEM);
    cudaFuncSetAttribute(gemm_tc_cat<0, true >,        cudaFuncAttributeMaxDynamicSharedMemorySize, GEMM_SMEM);
    cudaFuncSetAttribute(gemm_tc_cat<1, false>,        cudaFuncAttributeMaxDynamicSharedMemorySize, GEMM_SMEM);

    const int GB = (NN + 127) / 128;                      // 391 tile-rows
    const dim3 GB2(GB, 2);
    const int WARP_BLKS  = (NN * 32 + 255) / 256;
    const int WARP_BLKS2 = (2 * NN * 32 + 255) / 256;

    // 0) pre-round all weight matrices to tf32 (bit-identical to in-loop cvt.rna)
    wconv_kernel<<<(WTF_TOTAL + 255) / 256, 256>>>(W_img, W_txt, img_W1, img_W2,
                                                   txt_W1, txt_W2, comb_W, fc_W);

    // 1) feature projections, img+txt fused (y=0: K=2048, y=1: K=768)
    gemm_tc<false, false, true><<<GB2, 256, GEMM_SMEM>>>(
        img_h, wtf + OFF_WIMG, nullptr, imgf, NN, 2048,
        txt_h, wtf + OFF_WTXT, nullptr, txtf, 768);

    // 2) gate MLP layer 1, img+txt fused (concat gather GEMM)
    gemm_tc_cat<0, true><<<GB2, 256, GEMM_SMEM>>>(
        emb, imgf, node_id, wtf + OFF_IW1, img_b1, h1a, NN,
        txtf, wtf + OFF_TW1, txt_b1, h1b);

    // 3) gate MLP layer 2, img+txt fused
    gemm_tc<true, true, true><<<GB2, 256, GEMM_SMEM>>>(
        h1a, wtf + OFF_IW2, img_b2, h2a, NN, 128,
        h1b, wtf + OFF_TW2, txt_b2, h2b, 128);

    // 4) gate finalize, both paths
    gate_fin_dual<<<WARP_BLKS2, 256>>>(h2a, h2b, img_W3, txt_W3, img_b3, txt_b3,
                                       imgf, txtf, emb, node_id, imgv, txtv);

    // 5) combine gate + blend
    gemm_tc_cat<1, false><<<GB, 256, GEMM_SMEM>>>(
        imgv, txtv, nullptr, wtf + OFF_CW, comb_b, hb, NN,
        nullptr, nullptr, nullptr, nullptr);

    // 6) fc projection -> z
    gemm_tc<false, false, false><<<GB, 256, GEMM_SMEM>>>(
        hb, wtf + OFF_FW, nullptr, zb, NN, 128,
        nullptr, nullptr, nullptr, nullptr, 128);

    // 7) attention scalars
    attn_e_kernel<<<WARP_BLKS, 256>>>(zb, attn_a, es, ed);

    // 8) edge softmax + aggregate via CSR (no output atomics)
    zero_cnt_kernel<<<(NN + 255) / 256, 256>>>();
    hist_kernel<<<(NE + 255) / 256, 256>>>(dst);
    scan_kernel<<<1, 1024>>>();
    scatter_kernel<<<(NE + 255) / 256, 256>>>(src, dst);
    aggregate_kernel<<<(NN * 32 + 255) / 256, 256>>>(out);
}

// round 15
// speedup vs baseline: 3.6876x; 1.0710x over previous
#include <cuda_runtime.h>
#include <cstdint>

#define NN 50000
#define NE 800000
#define HID 128

// ---------------- scratch (static device arrays; no allocation) ----------------
__device__ float g_img_f[(size_t)NN * HID];
__device__ float g_txt_f[(size_t)NN * HID];
__device__ float g_h1a  [(size_t)NN * HID];
__device__ float g_h1b  [(size_t)NN * HID];
__device__ float g_h2a  [(size_t)NN * HID];
__device__ float g_h2b  [(size_t)NN * HID];
__device__ float g_img_v[(size_t)NN * HID];
__device__ float g_txt_v[(size_t)NN * HID];
__device__ float g_hbuf [(size_t)NN * HID];
__device__ float g_z    [(size_t)NN * HID];
__device__ float g_esrc [NN];
__device__ float g_edst [NN];
// CSR edge machinery
__device__ int   g_cnt  [NN];
__device__ int   g_start[NN];
__device__ int   g_cur  [NN];
__device__ int   g_srcs [NE];
__device__ float g_es_s [NE];

// -------- tf32 weights, PRE-PADDED to the SMEM stage layout --------
// per 16-row k-tile: 16 rows x 136 floats = 2176 floats = 8704 bytes (bulk unit)
#define BTILE_FL 2176
#define BTILE_BYTES 8704
// padded offsets (floats): src K rows -> (K/16) tiles
#define PWIMG 0         /* 2048 rows -> 128 tiles */
#define PWTXT 278528    /*  768 rows ->  48 tiles */
#define PIW1  382976    /*  256 rows ->  16 tiles */
#define PIW2  417792    /*  128 rows ->   8 tiles */
#define PTW1  435200
#define PTW2  470016
#define PCW   487424
#define PFW   522240
#define PTOT  539648
__device__ float g_wtf[PTOT];

// source (unpadded) element-range boundaries for wconv
#define SWTXT 262144
#define SIW1  360448
#define SIW2  393216
#define STW1  409600
#define STW2  442368
#define SCW   458752
#define SFW   491520
#define STOT  507904

// ---------------------------------------------------------------------------
// tf32 / async helpers
// ---------------------------------------------------------------------------
__device__ __forceinline__ uint32_t f2tf(float f) {
    uint32_t r;
    asm("cvt.rna.tf32.f32 %0, %1;" : "=r"(r) : "f"(f));
    return r;
}

__device__ __forceinline__ void mma_tf32(float* c,
                                         uint32_t a0, uint32_t a1, uint32_t a2, uint32_t a3,
                                         uint32_t b0, uint32_t b1)
{
    asm volatile(
        "mma.sync.aligned.m16n8k8.row.col.f32.tf32.tf32.f32 "
        "{%0,%1,%2,%3},{%4,%5,%6,%7},{%8,%9},{%0,%1,%2,%3};"
        : "+f"(c[0]), "+f"(c[1]), "+f"(c[2]), "+f"(c[3])
        : "r"(a0), "r"(a1), "r"(a2), "r"(a3), "r"(b0), "r"(b1));
}

__device__ __forceinline__ void cp16(uint32_t sdst, const void* gsrc, int predsz) {
    asm volatile("cp.async.cg.shared.global [%0], [%1], 16, %2;"
                 :: "r"(sdst), "l"(gsrc), "r"(predsz));
}
#define CP_COMMIT() asm volatile("cp.async.commit_group;")

__device__ __forceinline__ void mbar_init(uint32_t mb, uint32_t cnt) {
    asm volatile("mbarrier.init.shared.b64 [%0], %1;" :: "r"(mb), "r"(cnt) : "memory");
}
__device__ __forceinline__ void mbar_expect_tx(uint32_t mb, uint32_t bytes) {
    asm volatile("mbarrier.arrive.expect_tx.shared.b64 _, [%0], %1;"
                 :: "r"(mb), "r"(bytes) : "memory");
}
__device__ __forceinline__ void bulk_ld(uint32_t sdst, const void* gsrc,
                                        uint32_t bytes, uint32_t mb) {
    asm volatile("cp.async.bulk.shared::cluster.global.mbarrier::complete_tx::bytes "
                 "[%0], [%1], %2, [%3];"
                 :: "r"(sdst), "l"(gsrc), "r"(bytes), "r"(mb) : "memory");
}
__device__ __forceinline__ void mbar_wait(uint32_t mb, uint32_t parity) {
    asm volatile(
        "{\n\t.reg .pred P1;\n\t"
        "WAIT_LOOP_%=:\n\t"
        "mbarrier.try_wait.parity.acquire.cta.shared::cta.b64 P1, [%0], %1, 0x989680;\n\t"
        "@P1 bra.uni WAIT_DONE_%=;\n\t"
        "bra.uni WAIT_LOOP_%=;\n\t"
        "WAIT_DONE_%=:\n\t}"
        :: "r"(mb), "r"(parity) : "memory");
}

// SMEM: As[m][20] bank perm (20g+c)%32; Bs rows stride 136 -> (8c+g)%32 perm.
#define ASTR 20
#define NSTAGE 4
#define A_TILE_BYTES (128 * ASTR * 4)
#define GEMM_SMEM (NSTAGE * (A_TILE_BYTES + BTILE_BYTES))   // 75776 B

// weight tf32 pre-convert INTO padded stage layout
__global__ void wconv_kernel(const float* __restrict__ W_img, const float* __restrict__ W_txt,
                             const float* __restrict__ iW1,   const float* __restrict__ iW2,
                             const float* __restrict__ tW1,   const float* __restrict__ tW2,
                             const float* __restrict__ cW,    const float* __restrict__ fW)
{
    int i = blockIdx.x * blockDim.x + threadIdx.x;
    if (i >= STOT) return;
    const float* src; int local; int pbase;
    if      (i < SWTXT) { src = W_img; local = i;         pbase = PWIMG; }
    else if (i < SIW1)  { src = W_txt; local = i - SWTXT; pbase = PWTXT; }
    else if (i < SIW2)  { src = iW1;   local = i - SIW1;  pbase = PIW1; }
    else if (i < STW1)  { src = iW2;   local = i - SIW2;  pbase = PIW2; }
    else if (i < STW2)  { src = tW1;   local = i - STW1;  pbase = PTW1; }
    else if (i < SCW)   { src = tW2;   local = i - STW2;  pbase = PTW2; }
    else if (i < SFW)   { src = cW;    local = i - SCW;   pbase = PCW; }
    else                { src = fW;    local = i - SFW;   pbase = PFW; }
    int k = local >> 7, n = local & 127;
    g_wtf[pbase + (k >> 4) * BTILE_FL + (k & 15) * 136 + n] =
        __uint_as_float(f2tf(src[local]));
}

// ---------------------------------------------------------------------------
// tensor-core SGEMM (tf32): A via 4-stage cp.async ring; B via single-thread
// cp.async.bulk from pre-padded tf32 weights (mbarrier complete_tx).
// C[M x 128] = act(A[M x K] @ Bpad (+bias)), K % 16 == 0, K/16 >= 3
// block 128x128, BK=16, 8 warps in 4(M)x2(N), warp tile 32x64
// ---------------------------------------------------------------------------
template<bool BIAS, bool RELU, bool DUAL>
__global__ __launch_bounds__(256, 2)
void gemm_tc(const float* __restrict__ A0, const float* __restrict__ B0,
             const float* __restrict__ bias0, float* __restrict__ C0, int M, int K0,
             const float* A1, const float* B1, const float* bias1, float* C1, int K1)
{
    extern __shared__ char smem_raw[];
    float (*As)[128][ASTR] = (float(*)[128][ASTR])smem_raw;
    float (*Bs)[BTILE_FL]  = (float(*)[BTILE_FL])(smem_raw + NSTAGE * A_TILE_BYTES);
    __shared__ uint64_t s_mbar[NSTAGE];

    const bool alt = DUAL && (blockIdx.y != 0);
    const float* A    = alt ? A1 : A0;
    const float* B    = alt ? B1 : B0;   // padded tf32
    const float* bias = alt ? bias1 : bias0;
    float* C          = alt ? C1 : C0;
    const int K       = alt ? K1 : K0;

    const int tid  = threadIdx.x;
    const int warp = tid >> 5;
    const int lane = tid & 31;
    const int m0   = blockIdx.x * 128;

    const int wmb = (warp & 3) * 32;
    const int wnb = (warp >> 2) * 64;

    const int ar0 = tid >> 2;
    const int ac0 = (tid & 3) << 2;

    const uint32_t mb0 = (uint32_t)__cvta_generic_to_shared(&s_mbar[0]);
    const uint32_t bs0 = (uint32_t)__cvta_generic_to_shared(&Bs[0][0]);

    if (tid == 0) {
#pragma unroll
        for (int s = 0; s < NSTAGE; s++) mbar_init(mb0 + s * 8, 1);
        asm volatile("fence.proxy.async.shared::cta;" ::: "memory");
    }
    __syncthreads();

    float acc[2][8][4];
#pragma unroll
    for (int i = 0; i < 2; i++)
#pragma unroll
        for (int j = 0; j < 8; j++)
#pragma unroll
            for (int v = 0; v < 4; v++) acc[i][j][v] = 0.f;

    auto load_a = [&](int s, int k0) {
#pragma unroll
        for (int p = 0; p < 2; p++) {
            int row = ar0 + p * 64;
            int gr  = m0 + row;
            cp16((uint32_t)__cvta_generic_to_shared(&As[s][row][ac0]),
                 A + (size_t)gr * K + k0 + ac0, gr < M ? 16 : 0);
        }
    };
    auto load_b = [&](int s, int t) {
        mbar_expect_tx(mb0 + s * 8, BTILE_BYTES);
        bulk_ld(bs0 + s * BTILE_BYTES, B + (size_t)t * BTILE_FL, BTILE_BYTES, mb0 + s * 8);
    };

    const int T = K >> 4;
    load_a(0, 0);  CP_COMMIT();
    load_a(1, 16); CP_COMMIT();
    load_a(2, 32); CP_COMMIT();
    if (tid == 0) { load_b(0, 0); load_b(1, 1); load_b(2, 2); }

    for (int t = 0; t < T; t++) {
        if (t < T - 2)       asm volatile("cp.async.wait_group 2;");
        else if (t == T - 2) asm volatile("cp.async.wait_group 1;");
        else                 asm volatile("cp.async.wait_group 0;");
        mbar_wait(mb0 + (t & 3) * 8, (t >> 2) & 1);
        __syncthreads();

        if (t + 3 < T) {
            load_a((t + 3) & 3, (t + 3) << 4);
            CP_COMMIT();
            if (tid == 0) load_b((t + 3) & 3, t + 3);
        }

        const int buf = t & 3;
        const float* bsl = Bs[buf];
#pragma unroll
        for (int ks = 0; ks < 2; ks++) {
            const int kc = ks * 8 + (lane & 3);
            const int gm = lane >> 2;
            uint32_t af[2][4], bf[8][2];
#pragma unroll
            for (int mt = 0; mt < 2; mt++) {
                int m = wmb + mt * 16 + gm;
                af[mt][0] = f2tf(As[buf][m    ][kc    ]);
                af[mt][1] = f2tf(As[buf][m + 8][kc    ]);
                af[mt][2] = f2tf(As[buf][m    ][kc + 4]);
                af[mt][3] = f2tf(As[buf][m + 8][kc + 4]);
            }
#pragma unroll
            for (int nt = 0; nt < 8; nt++) {
                int n = wnb + nt * 8 + gm;
                bf[nt][0] = __float_as_uint(bsl[kc * 136 + n]);       // pre-rounded tf32
                bf[nt][1] = __float_as_uint(bsl[(kc + 4) * 136 + n]);
            }
#pragma unroll
            for (int mt = 0; mt < 2; mt++)
#pragma unroll
                for (int nt = 0; nt < 8; nt++)
                    mma_tf32(acc[mt][nt], af[mt][0], af[mt][1], af[mt][2], af[mt][3],
                             bf[nt][0], bf[nt][1]);
        }
    }

    // ---- epilogue ----
#pragma unroll
    for (int mt = 0; mt < 2; mt++) {
        int r0 = m0 + wmb + mt * 16 + (lane >> 2);
#pragma unroll
        for (int nt = 0; nt < 8; nt++) {
            int c = wnb + nt * 8 + ((lane & 3) << 1);
            float bb0 = 0.f, bb1 = 0.f;
            if (BIAS) { bb0 = bias[c]; bb1 = bias[c + 1]; }
            float v0 = acc[mt][nt][0] + bb0, v1 = acc[mt][nt][1] + bb1;
            float v2 = acc[mt][nt][2] + bb0, v3 = acc[mt][nt][3] + bb1;
            if (RELU) {
                v0 = fmaxf(v0, 0.f); v1 = fmaxf(v1, 0.f);
                v2 = fmaxf(v2, 0.f); v3 = fmaxf(v3, 0.f);
            }
            if (r0 < M)     *(float2*)(C + (size_t)r0 * HID + c)       = make_float2(v0, v1);
            if (r0 + 8 < M) *(float2*)(C + (size_t)(r0 + 8) * HID + c) = make_float2(v2, v3);
        }
    }
}

// ---------------------------------------------------------------------------
// tensor-core concat SGEMM: A row r = [ P[gidx?gidx[r]:r] | Q[r] ], K = 256
// MODE 0 (DUAL ok): C = relu(A@B + bias)
// MODE 1: gate = A@B + bias; C = gate*P + (1-gate)*Q
// B via bulk from padded tf32 weights.
// ---------------------------------------------------------------------------
template<int MODE, bool DUAL>
__global__ __launch_bounds__(256, 2)
void gemm_tc_cat(const float* __restrict__ P,
                 const float* __restrict__ Q0, const int* __restrict__ gidx,
                 const float* __restrict__ B0, const float* __restrict__ bias0,
                 float* __restrict__ C0, int M,
                 const float* Q1, const float* B1, const float* bias1, float* C1)
{
    extern __shared__ char smem_raw[];
    float (*As)[128][ASTR] = (float(*)[128][ASTR])smem_raw;
    float (*Bs)[BTILE_FL]  = (float(*)[BTILE_FL])(smem_raw + NSTAGE * A_TILE_BYTES);
    __shared__ uint64_t s_mbar[NSTAGE];

    const bool alt = DUAL && (blockIdx.y != 0);
    const float* Q    = alt ? Q1 : Q0;
    const float* B    = alt ? B1 : B0;
    const float* bias = alt ? bias1 : bias0;
    float* C          = alt ? C1 : C0;

    const int tid  = threadIdx.x;
    const int warp = tid >> 5;
    const int lane = tid & 31;
    const int m0   = blockIdx.x * 128;

    const int wmb = (warp & 3) * 32;
    const int wnb = (warp >> 2) * 64;

    const int ar0 = tid >> 2;
    const int ac0 = (tid & 3) << 2;

    const uint32_t mb0 = (uint32_t)__cvta_generic_to_shared(&s_mbar[0]);
    const uint32_t bs0 = (uint32_t)__cvta_generic_to_shared(&Bs[0][0]);

    if (tid == 0) {
#pragma unroll
        for (int s = 0; s < NSTAGE; s++) mbar_init(mb0 + s * 8, 1);
        asm volatile("fence.proxy.async.shared::cta;" ::: "memory");
    }
    __syncthreads();

    int grow[2], rgat[2], pr[2];
#pragma unroll
    for (int p = 0; p < 2; p++) {
        int row = ar0 + p * 64;
        int gr  = m0 + row;
        grow[p] = gr;
        pr[p]   = (gr < M) ? 16 : 0;
        rgat[p] = (MODE == 0) ? ((gr < M) ? gidx[gr] : 0) : gr;
    }

    float acc[2][8][4];
#pragma unroll
    for (int i = 0; i < 2; i++)
#pragma unroll
        for (int j = 0; j < 8; j++)
#pragma unroll
            for (int v = 0; v < 4; v++) acc[i][j][v] = 0.f;

    auto load_a = [&](int s, int k0) {
        const float* S  = (k0 < 128) ? P : Q;
        const int cbase = (k0 < 128) ? k0 : (k0 - 128);
        const bool gath = (k0 < 128);
#pragma unroll
        for (int p = 0; p < 2; p++) {
            int row = ar0 + p * 64;
            int rr  = gath ? rgat[p] : grow[p];
            cp16((uint32_t)__cvta_generic_to_shared(&As[s][row][ac0]),
                 S + (size_t)rr * HID + cbase + ac0, pr[p]);
        }
    };
    auto load_b = [&](int s, int t) {
        mbar_expect_tx(mb0 + s * 8, BTILE_BYTES);
        bulk_ld(bs0 + s * BTILE_BYTES, B + (size_t)t * BTILE_FL, BTILE_BYTES, mb0 + s * 8);
    };

    const int T = 16;  // K = 256
    load_a(0, 0);  CP_COMMIT();
    load_a(1, 16); CP_COMMIT();
    load_a(2, 32); CP_COMMIT();
    if (tid == 0) { load_b(0, 0); load_b(1, 1); load_b(2, 2); }

    for (int t = 0; t < T; t++) {
        if (t < T - 2)       asm volatile("cp.async.wait_group 2;");
        else if (t == T - 2) asm volatile("cp.async.wait_group 1;");
        else                 asm volatile("cp.async.wait_group 0;");
        mbar_wait(mb0 + (t & 3) * 8, (t >> 2) & 1);
        __syncthreads();

        if (t + 3 < T) {
            load_a((t + 3) & 3, (t + 3) << 4);
            CP_COMMIT();
            if (tid == 0) load_b((t + 3) & 3, t + 3);
        }

        const int buf = t & 3;
        const float* bsl = Bs[buf];
#pragma unroll
        for (int ks = 0; ks < 2; ks++) {
            const int kc = ks * 8 + (lane & 3);
            const int gm = lane >> 2;
            uint32_t af[2][4], bf[8][2];
#pragma unroll
            for (int mt = 0; mt < 2; mt++) {
                int m = wmb + mt * 16 + gm;
                af[mt][0] = f2tf(As[buf][m    ][kc    ]);
                af[mt][1] = f2tf(As[buf][m + 8][kc    ]);
                af[mt][2] = f2tf(As[buf][m    ][kc + 4]);
                af[mt][3] = f2tf(As[buf][m + 8][kc + 4]);
            }
#pragma unroll
            for (int nt = 0; nt < 8; nt++) {
                int n = wnb + nt * 8 + gm;
                bf[nt][0] = __float_as_uint(bsl[kc * 136 + n]);
                bf[nt][1] = __float_as_uint(bsl[(kc + 4) * 136 + n]);
            }
#pragma unroll
            for (int mt = 0; mt < 2; mt++)
#pragma unroll
                for (int nt = 0; nt < 8; nt++)
                    mma_tf32(acc[mt][nt], af[mt][0], af[mt][1], af[mt][2], af[mt][3],
                             bf[nt][0], bf[nt][1]);
        }
    }

#pragma unroll
    for (int mt = 0; mt < 2; mt++) {
        int r0 = m0 + wmb + mt * 16 + (lane >> 2);
#pragma unroll
        for (int nt = 0; nt < 8; nt++) {
            int c = wnb + nt * 8 + ((lane & 3) << 1);
            float bb0 = bias[c], bb1 = bias[c + 1];
            float v0 = acc[mt][nt][0] + bb0, v1 = acc[mt][nt][1] + bb1;
            float v2 = acc[mt][nt][2] + bb0, v3 = acc[mt][nt][3] + bb1;
#pragma unroll
            for (int h = 0; h < 2; h++) {
                int r = r0 + h * 8;
                if (r >= M) continue;
                float g0 = h ? v2 : v0, g1 = h ? v3 : v1;
                float o0, o1;
                if (MODE == 0) {
                    o0 = fmaxf(g0, 0.f);
                    o1 = fmaxf(g1, 0.f);
                } else {
                    float2 pv = *(const float2*)(P + (size_t)r * HID + c);
                    float2 qv = *(const float2*)(Q + (size_t)r * HID + c);
                    o0 = g0 * pv.x + (1.f - g0) * qv.x;
                    o1 = g1 * pv.y + (1.f - g1) * qv.y;
                }
                *(float2*)(C + (size_t)r * HID + c) = make_float2(o0, o1);
            }
        }
    }
}

// ---------------------------------------------------------------------------
// gate finalize, dual (img path then txt path): one warp per (set, node)
// ---------------------------------------------------------------------------
__global__ void gate_fin_dual(const float* __restrict__ h2a, const float* __restrict__ h2b,
                              const float* __restrict__ W3a, const float* __restrict__ W3b,
                              const float* __restrict__ b3a, const float* __restrict__ b3b,
                              const float* __restrict__ fa,  const float* __restrict__ fb,
                              const float* __restrict__ emb, const int* __restrict__ nid,
                              float* __restrict__ va, float* __restrict__ vb)
{
    int id = (blockIdx.x * blockDim.x + threadIdx.x) >> 5;
    int lane = threadIdx.x & 31;
    if (id >= 2 * NN) return;
    int set = (id >= NN);
    int w = id - set * NN;
    const float* h2 = set ? h2b : h2a;
    const float* W3 = set ? W3b : W3a;
    const float* b3 = set ? b3b : b3a;
    const float* f  = set ? fb  : fa;
    float* v_out    = set ? vb  : va;

    float4 h4 = *(const float4*)(h2 + (size_t)w * HID + lane * 4);
    float4 w4 = *(const float4*)(W3 + lane * 4);
    float d = h4.x * w4.x + h4.y * w4.y + h4.z * w4.z + h4.w * w4.w;
#pragma unroll
    for (int o = 16; o; o >>= 1) d += __shfl_xor_sync(0xffffffffu, d, o);
    float g = 1.f / (1.f + expf(-(d + b3[0])));
    int e = nid[w];
    float4 fv = *(const float4*)(f + (size_t)w * HID + lane * 4);
    float4 ev = *(const float4*)(emb + (size_t)e * HID + lane * 4);
    float4 o4;
    o4.x = g * fv.x + (1.f - g) * ev.x;
    o4.y = g * fv.y + (1.f - g) * ev.y;
    o4.z = g * fv.z + (1.f - g) * ev.z;
    o4.w = g * fv.w + (1.f - g) * ev.w;
    *(float4*)(v_out + (size_t)w * HID + lane * 4) = o4;
}

// e_src = z . a1, e_dst = z . a2  (one warp per node)
__global__ void attn_e_kernel(const float* __restrict__ z,
                              const float* __restrict__ a,
                              float* __restrict__ es, float* __restrict__ ed)
{
    int w = (blockIdx.x * blockDim.x + threadIdx.x) >> 5;
    int lane = threadIdx.x & 31;
    if (w >= NN) return;
    float4 zv = *(const float4*)(z + (size_t)w * HID + lane * 4);
    float4 a1 = *(const float4*)(a + lane * 4);
    float4 a2 = *(const float4*)(a + HID + lane * 4);
    float d1 = zv.x * a1.x + zv.y * a1.y + zv.z * a1.z + zv.w * a1.w;
    float d2 = zv.x * a2.x + zv.y * a2.y + zv.z * a2.z + zv.w * a2.w;
#pragma unroll
    for (int o = 16; o; o >>= 1) {
        d1 += __shfl_xor_sync(0xffffffffu, d1, o);
        d2 += __shfl_xor_sync(0xffffffffu, d2, o);
    }
    if (lane == 0) { es[w] = d1; ed[w] = d2; }
}

// ---------------------------------------------------------------------------
// Edge phase: CSR by dst, warp-per-dst softmax aggregate (no output atomics)
// ---------------------------------------------------------------------------
__global__ void zero_cnt_kernel()
{
    int i = blockIdx.x * blockDim.x + threadIdx.x;
    if (i < NN) { g_cnt[i] = 0; g_cur[i] = 0; }
}

__global__ void hist_kernel(const int* __restrict__ dst)
{
    int e = blockIdx.x * blockDim.x + threadIdx.x;
    if (e < NE) atomicAdd(&g_cnt[dst[e]], 1);
}

// single-block exclusive scan over g_cnt -> g_start (1024 threads)
__global__ void scan_kernel()
{
    __shared__ int warp_sums[32];
    __shared__ int s_carry;
    int tid = threadIdx.x, lane = tid & 31, wid = tid >> 5;
    if (tid == 0) s_carry = 0;
    __syncthreads();
    for (int base = 0; base < NN; base += 1024) {
        int i = base + tid;
        int v = (i < NN) ? g_cnt[i] : 0;
        int x = v;
#pragma unroll
        for (int o = 1; o < 32; o <<= 1) {
            int y = __shfl_up_sync(0xffffffffu, x, o);
            if (lane >= o) x += y;
        }
        if (lane == 31) warp_sums[wid] = x;
        __syncthreads();
        if (wid == 0) {
            int ws = warp_sums[lane];
#pragma unroll
            for (int o = 1; o < 32; o <<= 1) {
                int y = __shfl_up_sync(0xffffffffu, ws, o);
                if (lane >= o) ws += y;
            }
            warp_sums[lane] = ws;
        }
        __syncthreads();
        int incl = x + (wid ? warp_sums[wid - 1] : 0);
        int carry = s_carry;
        if (i < NN) g_start[i] = carry + incl - v;
        __syncthreads();
        if (tid == 0) s_carry = carry + warp_sums[31];
        __syncthreads();
    }
}

__global__ void scatter_kernel(const int* __restrict__ src, const int* __restrict__ dst)
{
    int e = blockIdx.x * blockDim.x + threadIdx.x;
    if (e >= NE) return;
    int s = src[e], d = dst[e];
    float v = g_esrc[s] + g_edst[d];
    v = (v > 0.f) ? v : 0.01f * v;
    int pos = atomicAdd(&g_cur[d], 1);
    int idx = g_start[d] + pos;
    g_srcs[idx] = s;
    g_es_s[idx] = v;
}

__global__ __launch_bounds__(256)
void aggregate_kernel(float* __restrict__ out)
{
    __shared__ float ws[8][32];
    __shared__ int   ss[8][32];
    int w    = (blockIdx.x * blockDim.x + threadIdx.x) >> 5;
    int lane = threadIdx.x & 31;
    int wib  = (threadIdx.x >> 5);
    if (w >= NN) return;

    int s0  = g_start[w];
    int deg = g_cnt[w];

    float mx = -3.402823466e38f;
    for (int j = lane; j < deg; j += 32) mx = fmaxf(mx, g_es_s[s0 + j]);
#pragma unroll
    for (int o = 16; o; o >>= 1) mx = fmaxf(mx, __shfl_xor_sync(0xffffffffu, mx, o));

    float dsum = 0.f;
    for (int j = lane; j < deg; j += 32) dsum += expf(g_es_s[s0 + j] - mx);
#pragma unroll
    for (int o = 16; o; o >>= 1) dsum += __shfl_xor_sync(0xffffffffu, dsum, o);
    float inv = 1.f / fmaxf(dsum, 1e-20f);

    float4 acc = make_float4(0.f, 0.f, 0.f, 0.f);
    for (int base = 0; base < deg; base += 32) {
        int j = base + lane;
        float wv = 0.f; int sj = 0;
        if (j < deg) {
            wv = expf(g_es_s[s0 + j] - mx) * inv;
            sj = g_srcs[s0 + j];
        }
        ws[wib][lane] = wv;
        ss[wib][lane] = sj;
        __syncwarp();
        int lim = min(32, deg - base);
        for (int jj = 0; jj < lim; jj++) {
            float wj = ws[wib][jj];
            const float4 zv = *(const float4*)(g_z + (size_t)ss[wib][jj] * HID + lane * 4);
            acc.x += wj * zv.x; acc.y += wj * zv.y;
            acc.z += wj * zv.z; acc.w += wj * zv.w;
        }
        __syncwarp();
    }
    *(float4*)(out + (size_t)w * HID + lane * 4) = acc;
}

// ---------------------------------------------------------------------------
extern "C" void kernel_launch(void* const* d_in, const int* in_sizes, int n_in,
                              void* d_out, int out_size)
{
    const int*   node_id = (const int*)  d_in[0];
    const float* img_h   = (const float*)d_in[1];
    const float* txt_h   = (const float*)d_in[2];
    const int*   src     = (const int*)  d_in[3];
    const int*   dst     = (const int*)  d_in[4];
    const float* emb     = (const float*)d_in[5];
    const float* W_img   = (const float*)d_in[6];
    const float* img_W1  = (const float*)d_in[7];
    const float* img_b1  = (const float*)d_in[8];
    const float* img_W2  = (const float*)d_in[9];
    const float* img_b2  = (const float*)d_in[10];
    const float* img_W3  = (const float*)d_in[11];
    const float* img_b3  = (const float*)d_in[12];
    const float* W_txt   = (const float*)d_in[13];
    const float* txt_W1  = (const float*)d_in[14];
    const float* txt_b1  = (const float*)d_in[15];
    const float* txt_W2  = (const float*)d_in[16];
    const float* txt_b2  = (const float*)d_in[17];
    const float* txt_W3  = (const float*)d_in[18];
    const float* txt_b3  = (const float*)d_in[19];
    const float* comb_W  = (const float*)d_in[20];
    const float* comb_b  = (const float*)d_in[21];
    const float* fc_W    = (const float*)d_in[22];
    const float* attn_a  = (const float*)d_in[23];
    float* out = (float*)d_out;

    float *imgf, *txtf, *h1a, *h1b, *h2a, *h2b, *imgv, *txtv, *hb, *zb, *es, *ed, *wtf;
    cudaGetSymbolAddress((void**)&imgf, g_img_f);
    cudaGetSymbolAddress((void**)&txtf, g_txt_f);
    cudaGetSymbolAddress((void**)&h1a,  g_h1a);
    cudaGetSymbolAddress((void**)&h1b,  g_h1b);
    cudaGetSymbolAddress((void**)&h2a,  g_h2a);
    cudaGetSymbolAddress((void**)&h2b,  g_h2b);
    cudaGetSymbolAddress((void**)&imgv, g_img_v);
    cudaGetSymbolAddress((void**)&txtv, g_txt_v);
    cudaGetSymbolAddress((void**)&hb,   g_hbuf);
    cudaGetSymbolAddress((void**)&zb,   g_z);
    cudaGetSymbolAddress((void**)&es,   g_esrc);
    cudaGetSymbolAddress((void**)&ed,   g_edst);
    cudaGetSymbolAddress((void**)&wtf,  g_wtf);

    cudaFuncSetAttribute(gemm_tc<false, false, true >, cudaFuncAttributeMaxDynamicSharedMemorySize, GEMM_SMEM);
    cudaFuncSetAttribute(gemm_tc<true,  true,  true >, cudaFuncAttributeMaxDynamicSharedMemorySize, GEMM_SMEM);
    cudaFuncSetAttribute(gemm_tc<false, false, false>, cudaFuncAttributeMaxDynamicSharedMemorySize, GEMM_SMEM);
    cudaFuncSetAttribute(gemm_tc_cat<0, true >,        cudaFuncAttributeMaxDynamicSharedMemorySize, GEMM_SMEM);
    cudaFuncSetAttribute(gemm_tc_cat<1, false>,        cudaFuncAttributeMaxDynamicSharedMemorySize, GEMM_SMEM);

    const int GB = (NN + 127) / 128;                      // 391 tile-rows
    const dim3 GB2(GB, 2);
    const int WARP_BLKS  = (NN * 32 + 255) / 256;
    const int WARP_BLKS2 = (2 * NN * 32 + 255) / 256;

    // 0) pre-round all weight matrices to tf32 into the padded stage layout
    wconv_kernel<<<(STOT + 255) / 256, 256>>>(W_img, W_txt, img_W1, img_W2,
                                              txt_W1, txt_W2, comb_W, fc_W);

    // 1) feature projections, img+txt fused (y=0: K=2048, y=1: K=768)
    gemm_tc<false, false, true><<<GB2, 256, GEMM_SMEM>>>(
        img_h, wtf + PWIMG, nullptr, imgf, NN, 2048,
        txt_h, wtf + PWTXT, nullptr, txtf, 768);

    // 2) gate MLP layer 1, img+txt fused (concat gather GEMM)
    gemm_tc_cat<0, true><<<GB2, 256, GEMM_SMEM>>>(
        emb, imgf, node_id, wtf + PIW1, img_b1, h1a, NN,
        txtf, wtf + PTW1, txt_b1, h1b);

    // 3) gate MLP layer 2, img+txt fused
    gemm_tc<true, true, true><<<GB2, 256, GEMM_SMEM>>>(
        h1a, wtf + PIW2, img_b2, h2a, NN, 128,
        h1b, wtf + PTW2, txt_b2, h2b, 128);

    // 4) gate finalize, both paths
    gate_fin_dual<<<WARP_BLKS2, 256>>>(h2a, h2b, img_W3, txt_W3, img_b3, txt_b3,
                                       imgf, txtf, emb, node_id, imgv, txtv);

    // 5) combine gate + blend
    gemm_tc_cat<1, false><<<GB, 256, GEMM_SMEM>>>(
        imgv, txtv, nullptr, wtf + PCW, comb_b, hb, NN,
        nullptr, nullptr, nullptr, nullptr);

    // 6) fc projection -> z
    gemm_tc<false, false, false><<<GB, 256, GEMM_SMEM>>>(
        hb, wtf + PFW, nullptr, zb, NN, 128,
        nullptr, nullptr, nullptr, nullptr, 128);

    // 7) attention scalars
    attn_e_kernel<<<WARP_BLKS, 256>>>(zb, attn_a, es, ed);

    // 8) edge softmax + aggregate via CSR (no output atomics)
    zero_cnt_kernel<<<(NN + 255) / 256, 256>>>();
    hist_kernel<<<(NE + 255) / 256, 256>>>(dst);
    scan_kernel<<<1, 1024>>>();
    scatter_kernel<<<(NE + 255) / 256, 256>>>(src, dst);
    aggregate_kernel<<<(NN * 32 + 255) / 256, 256>>>(out);
}

// round 16
// speedup vs baseline: 3.8946x; 1.0561x over previous
#include <cuda_runtime.h>
#include <cuda.h>
#include <cstdint>

#define NN 50000
#define NE 800000
#define HID 128

// ---------------- scratch (static device arrays; no allocation) ----------------
__device__ float g_img_f[(size_t)NN * HID];
__device__ float g_txt_f[(size_t)NN * HID];
__device__ float g_h1a  [(size_t)NN * HID];
__device__ float g_h1b  [(size_t)NN * HID];
__device__ float g_h2a  [(size_t)NN * HID];
__device__ float g_h2b  [(size_t)NN * HID];
__device__ float g_img_v[(size_t)NN * HID];
__device__ float g_txt_v[(size_t)NN * HID];
__device__ float g_hbuf [(size_t)NN * HID];
__device__ float g_z    [(size_t)NN * HID];
__device__ float g_esrc [NN];
__device__ float g_edst [NN];
// CSR edge machinery
__device__ int   g_cnt  [NN];
__device__ int   g_start[NN];
__device__ int   g_cur  [NN];
__device__ int   g_srcs [NE];
__device__ float g_es_s [NE];

// -------- tf32 weights, PRE-PADDED to the SMEM stage layout --------
#define BTILE_FL 2176
#define BTILE_BYTES 8704
#define PWIMG 0
#define PWTXT 278528
#define PIW1  382976
#define PIW2  417792
#define PTW1  435200
#define PTW2  470016
#define PCW   487424
#define PFW   522240
#define PTOT  539648
__device__ float g_wtf[PTOT];

#define SWTXT 262144
#define SIW1  360448
#define SIW2  393216
#define STW1  409600
#define STW2  442368
#define SCW   458752
#define SFW   491520
#define STOT  507904

// ---------------------------------------------------------------------------
// tf32 / async helpers
// ---------------------------------------------------------------------------
__device__ __forceinline__ uint32_t f2tf(float f) {
    uint32_t r;
    asm("cvt.rna.tf32.f32 %0, %1;" : "=r"(r) : "f"(f));
    return r;
}

__device__ __forceinline__ void mma_tf32(float* c,
                                         uint32_t a0, uint32_t a1, uint32_t a2, uint32_t a3,
                                         uint32_t b0, uint32_t b1)
{
    asm volatile(
        "mma.sync.aligned.m16n8k8.row.col.f32.tf32.tf32.f32 "
        "{%0,%1,%2,%3},{%4,%5,%6,%7},{%8,%9},{%0,%1,%2,%3};"
        : "+f"(c[0]), "+f"(c[1]), "+f"(c[2]), "+f"(c[3])
        : "r"(a0), "r"(a1), "r"(a2), "r"(a3), "r"(b0), "r"(b1));
}

__device__ __forceinline__ void cp16(uint32_t sdst, const void* gsrc, int predsz) {
    asm volatile("cp.async.cg.shared.global [%0], [%1], 16, %2;"
                 :: "r"(sdst), "l"(gsrc), "r"(predsz));
}
#define CP_COMMIT() asm volatile("cp.async.commit_group;")

__device__ __forceinline__ void mbar_init(uint32_t mb, uint32_t cnt) {
    asm volatile("mbarrier.init.shared.b64 [%0], %1;" :: "r"(mb), "r"(cnt) : "memory");
}
__device__ __forceinline__ void mbar_expect_tx(uint32_t mb, uint32_t bytes) {
    asm volatile("mbarrier.arrive.expect_tx.shared.b64 _, [%0], %1;"
                 :: "r"(mb), "r"(bytes) : "memory");
}
__device__ __forceinline__ void bulk_ld(uint32_t sdst, const void* gsrc,
                                        uint32_t bytes, uint32_t mb) {
    asm volatile("cp.async.bulk.shared::cluster.global.mbarrier::complete_tx::bytes "
                 "[%0], [%1], %2, [%3];"
                 :: "r"(sdst), "l"(gsrc), "r"(bytes), "r"(mb) : "memory");
}
__device__ __forceinline__ void tma_ld_2d(uint32_t sdst, const CUtensorMap* tm,
                                          int cx, int cy, uint32_t mb) {
    asm volatile("cp.async.bulk.tensor.2d.shared::cta.global.tile.mbarrier::complete_tx::bytes "
                 "[%0], [%1, {%2, %3}], [%4];"
                 :: "r"(sdst), "l"(tm), "r"(cx), "r"(cy), "r"(mb) : "memory");
}
__device__ __forceinline__ void mbar_wait(uint32_t mb, uint32_t parity) {
    asm volatile(
        "{\n\t.reg .pred P1;\n\t"
        "WAIT_LOOP_%=:\n\t"
        "mbarrier.try_wait.parity.acquire.cta.shared::cta.b64 P1, [%0], %1, 0x989680;\n\t"
        "@P1 bra.uni WAIT_DONE_%=;\n\t"
        "bra.uni WAIT_LOOP_%=;\n\t"
        "WAIT_DONE_%=:\n\t}"
        :: "r"(mb), "r"(parity) : "memory");
}

// ---------------------------------------------------------------------------
#define ASTR 20
#define NSTAGE 4
#define A_PAD_BYTES (128 * ASTR * 4)
#define ATMA_BYTES 8192
#define GEMM_SMEM_CAT (NSTAGE * (A_PAD_BYTES + BTILE_BYTES))   // 75776
#define GEMM_SMEM_TMA (NSTAGE * (ATMA_BYTES + BTILE_BYTES))    // 67584

// weight tf32 pre-convert INTO padded stage layout
__global__ void wconv_kernel(const float* __restrict__ W_img, const float* __restrict__ W_txt,
                             const float* __restrict__ iW1,   const float* __restrict__ iW2,
                             const float* __restrict__ tW1,   const float* __restrict__ tW2,
                             const float* __restrict__ cW,    const float* __restrict__ fW)
{
    int i = blockIdx.x * blockDim.x + threadIdx.x;
    if (i >= STOT) return;
    const float* src; int local; int pbase;
    if      (i < SWTXT) { src = W_img; local = i;         pbase = PWIMG; }
    else if (i < SIW1)  { src = W_txt; local = i - SWTXT; pbase = PWTXT; }
    else if (i < SIW2)  { src = iW1;   local = i - SIW1;  pbase = PIW1; }
    else if (i < STW1)  { src = iW2;   local = i - SIW2;  pbase = PIW2; }
    else if (i < STW2)  { src = tW1;   local = i - STW1;  pbase = PTW1; }
    else if (i < SCW)   { src = tW2;   local = i - STW2;  pbase = PTW2; }
    else if (i < SFW)   { src = cW;    local = i - SCW;   pbase = PCW; }
    else                { src = fW;    local = i - SFW;   pbase = PFW; }
    int k = local >> 7, n = local & 127;
    g_wtf[pbase + (k >> 4) * BTILE_FL + (k & 15) * 136 + n] =
        __uint_as_float(f2tf(src[local]));
}

// ---------------------------------------------------------------------------
// Dense tensor-core SGEMM: A via TMA (SW64, box 16x128), B via cp.async.bulk
// from pre-padded tf32 weights. Both complete on one mbarrier per stage.
// C[M x 128] = act(A[M x K] @ Bpad (+bias)), K % 16 == 0, K/16 >= 3
// block 128x128, BK=16, 8 warps 4(M)x2(N), warp tile 32x64
// ---------------------------------------------------------------------------
template<bool BIAS, bool RELU, bool DUAL>
__global__ __launch_bounds__(256, 2)
void gemm_tc_tma(const __grid_constant__ CUtensorMap tmA0,
                 const __grid_constant__ CUtensorMap tmA1,
                 const float* __restrict__ B0, const float* __restrict__ bias0,
                 float* __restrict__ C0, int M, int K0,
                 const float* B1, const float* bias1, float* C1, int K1)
{
    extern __shared__ __align__(1024) char smem_raw[];
    __shared__ uint64_t s_mbar[NSTAGE];

    const bool alt = DUAL && (blockIdx.y != 0);
    const CUtensorMap* tm = alt ? &tmA1 : &tmA0;
    const float* B    = alt ? B1 : B0;
    const float* bias = alt ? bias1 : bias0;
    float* C          = alt ? C1 : C0;
    const int K       = alt ? K1 : K0;

    const int tid  = threadIdx.x;
    const int warp = tid >> 5;
    const int lane = tid & 31;
    const int m0   = blockIdx.x * 128;

    const int wmb = (warp & 3) * 32;
    const int wnb = (warp >> 2) * 64;

    const uint32_t mb0 = (uint32_t)__cvta_generic_to_shared(&s_mbar[0]);
    const uint32_t as0 = (uint32_t)__cvta_generic_to_shared(smem_raw);
    const uint32_t bs0 = as0 + NSTAGE * ATMA_BYTES;
    const char* aptr = smem_raw;
    const float* bptr = (const float*)(smem_raw + NSTAGE * ATMA_BYTES);

    if (tid == 0) {
#pragma unroll
        for (int s = 0; s < NSTAGE; s++) mbar_init(mb0 + s * 8, 1);
        asm volatile("fence.proxy.async.shared::cta;" ::: "memory");
    }
    __syncthreads();

    float acc[2][8][4];
#pragma unroll
    for (int i = 0; i < 2; i++)
#pragma unroll
        for (int j = 0; j < 8; j++)
#pragma unroll
            for (int v = 0; v < 4; v++) acc[i][j][v] = 0.f;

    auto issue_stage = [&](int s, int t) {
        mbar_expect_tx(mb0 + s * 8, ATMA_BYTES + BTILE_BYTES);
        tma_ld_2d(as0 + s * ATMA_BYTES, tm, t * 16, m0, mb0 + s * 8);
        bulk_ld(bs0 + s * BTILE_BYTES, B + (size_t)t * BTILE_FL, BTILE_BYTES, mb0 + s * 8);
    };

    const int T = K >> 4;
    if (tid == 0) { issue_stage(0, 0); issue_stage(1, 1); issue_stage(2, 2); }

    for (int t = 0; t < T; t++) {
        mbar_wait(mb0 + (t & 3) * 8, (t >> 2) & 1);
        __syncthreads();

        if (t + 3 < T && tid == 0) issue_stage((t + 3) & 3, t + 3);

        const int buf = t & 3;
        const char*  asl = aptr + buf * ATMA_BYTES;
        const float* bsl = bptr + (size_t)buf * BTILE_FL;
#pragma unroll
        for (int ks = 0; ks < 2; ks++) {
            const int kc = ks * 8 + (lane & 3);
            const int gm = lane >> 2;
            uint32_t af[2][4], bf[8][2];
#pragma unroll
            for (int mt = 0; mt < 2; mt++) {
                int m = wmb + mt * 16 + gm;
                uint32_t o0 = (uint32_t)((m       << 6) + (kc       << 2));
                uint32_t o1 = (uint32_t)(((m + 8) << 6) + (kc       << 2));
                uint32_t o2 = (uint32_t)((m       << 6) + ((kc + 4) << 2));
                uint32_t o3 = (uint32_t)(((m + 8) << 6) + ((kc + 4) << 2));
                o0 ^= (o0 >> 3) & 0x30; o1 ^= (o1 >> 3) & 0x30;
                o2 ^= (o2 >> 3) & 0x30; o3 ^= (o3 >> 3) & 0x30;
                af[mt][0] = f2tf(*(const float*)(asl + o0));
                af[mt][1] = f2tf(*(const float*)(asl + o1));
                af[mt][2] = f2tf(*(const float*)(asl + o2));
                af[mt][3] = f2tf(*(const float*)(asl + o3));
            }
#pragma unroll
            for (int nt = 0; nt < 8; nt++) {
                int n = wnb + nt * 8 + gm;
                bf[nt][0] = __float_as_uint(bsl[kc * 136 + n]);
                bf[nt][1] = __float_as_uint(bsl[(kc + 4) * 136 + n]);
            }
#pragma unroll
            for (int mt = 0; mt < 2; mt++)
#pragma unroll
                for (int nt = 0; nt < 8; nt++)
                    mma_tf32(acc[mt][nt], af[mt][0], af[mt][1], af[mt][2], af[mt][3],
                             bf[nt][0], bf[nt][1]);
        }
    }

    // ---- epilogue ----
#pragma unroll
    for (int mt = 0; mt < 2; mt++) {
        int r0 = m0 + wmb + mt * 16 + (lane >> 2);
#pragma unroll
        for (int nt = 0; nt < 8; nt++) {
            int c = wnb + nt * 8 + ((lane & 3) << 1);
            float bb0 = 0.f, bb1 = 0.f;
            if (BIAS) { bb0 = bias[c]; bb1 = bias[c + 1]; }
            float v0 = acc[mt][nt][0] + bb0, v1 = acc[mt][nt][1] + bb1;
            float v2 = acc[mt][nt][2] + bb0, v3 = acc[mt][nt][3] + bb1;
            if (RELU) {
                v0 = fmaxf(v0, 0.f); v1 = fmaxf(v1, 0.f);
                v2 = fmaxf(v2, 0.f); v3 = fmaxf(v3, 0.f);
            }
            if (r0 < M)     *(float2*)(C + (size_t)r0 * HID + c)       = make_float2(v0, v1);
            if (r0 + 8 < M) *(float2*)(C + (size_t)(r0 + 8) * HID + c) = make_float2(v2, v3);
        }
    }
}

// ---------------------------------------------------------------------------
// tensor-core concat SGEMM (unchanged R15): A via LDGSTS ring, B via bulk.
// A row r = [ P[gidx?gidx[r]:r] | Q[r] ], K = 256
// MODE 0 (DUAL ok): C = relu(A@B + bias)
// MODE 1: gate = A@B + bias; C = gate*P + (1-gate)*Q
// ---------------------------------------------------------------------------
template<int MODE, bool DUAL>
__global__ __launch_bounds__(256, 2)
void gemm_tc_cat(const float* __restrict__ P,
                 const float* __restrict__ Q0, const int* __restrict__ gidx,
                 const float* __restrict__ B0, const float* __restrict__ bias0,
                 float* __restrict__ C0, int M,
                 const float* Q1, const float* B1, const float* bias1, float* C1)
{
    extern __shared__ __align__(1024) char smem_raw[];
    float (*As)[128][ASTR] = (float(*)[128][ASTR])smem_raw;
    float (*Bs)[BTILE_FL]  = (float(*)[BTILE_FL])(smem_raw + NSTAGE * A_PAD_BYTES);
    __shared__ uint64_t s_mbar[NSTAGE];

    const bool alt = DUAL && (blockIdx.y != 0);
    const float* Q    = alt ? Q1 : Q0;
    const float* B    = alt ? B1 : B0;
    const float* bias = alt ? bias1 : bias0;
    float* C          = alt ? C1 : C0;

    const int tid  = threadIdx.x;
    const int warp = tid >> 5;
    const int lane = tid & 31;
    const int m0   = blockIdx.x * 128;

    const int wmb = (warp & 3) * 32;
    const int wnb = (warp >> 2) * 64;

    const int ar0 = tid >> 2;
    const int ac0 = (tid & 3) << 2;

    const uint32_t mb0 = (uint32_t)__cvta_generic_to_shared(&s_mbar[0]);
    const uint32_t bs0 = (uint32_t)__cvta_generic_to_shared(&Bs[0][0]);

    if (tid == 0) {
#pragma unroll
        for (int s = 0; s < NSTAGE; s++) mbar_init(mb0 + s * 8, 1);
        asm volatile("fence.proxy.async.shared::cta;" ::: "memory");
    }
    __syncthreads();

    int grow[2], rgat[2], pr[2];
#pragma unroll
    for (int p = 0; p < 2; p++) {
        int row = ar0 + p * 64;
        int gr  = m0 + row;
        grow[p] = gr;
        pr[p]   = (gr < M) ? 16 : 0;
        rgat[p] = (MODE == 0) ? ((gr < M) ? gidx[gr] : 0) : gr;
    }

    float acc[2][8][4];
#pragma unroll
    for (int i = 0; i < 2; i++)
#pragma unroll
        for (int j = 0; j < 8; j++)
#pragma unroll
            for (int v = 0; v < 4; v++) acc[i][j][v] = 0.f;

    auto load_a = [&](int s, int k0) {
        const float* S  = (k0 < 128) ? P : Q;
        const int cbase = (k0 < 128) ? k0 : (k0 - 128);
        const bool gath = (k0 < 128);
#pragma unroll
        for (int p = 0; p < 2; p++) {
            int row = ar0 + p * 64;
            int rr  = gath ? rgat[p] : grow[p];
            cp16((uint32_t)__cvta_generic_to_shared(&As[s][row][ac0]),
                 S + (size_t)rr * HID + cbase + ac0, pr[p]);
        }
    };
    auto load_b = [&](int s, int t) {
        mbar_expect_tx(mb0 + s * 8, BTILE_BYTES);
        bulk_ld(bs0 + s * BTILE_BYTES, B + (size_t)t * BTILE_FL, BTILE_BYTES, mb0 + s * 8);
    };

    const int T = 16;  // K = 256
    load_a(0, 0);  CP_COMMIT();
    load_a(1, 16); CP_COMMIT();
    load_a(2, 32); CP_COMMIT();
    if (tid == 0) { load_b(0, 0); load_b(1, 1); load_b(2, 2); }

    for (int t = 0; t < T; t++) {
        if (t < T - 2)       asm volatile("cp.async.wait_group 2;");
        else if (t == T - 2) asm volatile("cp.async.wait_group 1;");
        else                 asm volatile("cp.async.wait_group 0;");
        mbar_wait(mb0 + (t & 3) * 8, (t >> 2) & 1);
        __syncthreads();

        if (t + 3 < T) {
            load_a((t + 3) & 3, (t + 3) << 4);
            CP_COMMIT();
            if (tid == 0) load_b((t + 3) & 3, t + 3);
        }

        const int buf = t & 3;
        const float* bsl = Bs[buf];
#pragma unroll
        for (int ks = 0; ks < 2; ks++) {
            const int kc = ks * 8 + (lane & 3);
            const int gm = lane >> 2;
            uint32_t af[2][4], bf[8][2];
#pragma unroll
            for (int mt = 0; mt < 2; mt++) {
                int m = wmb + mt * 16 + gm;
                af[mt][0] = f2tf(As[buf][m    ][kc    ]);
                af[mt][1] = f2tf(As[buf][m + 8][kc    ]);
                af[mt][2] = f2tf(As[buf][m    ][kc + 4]);
                af[mt][3] = f2tf(As[buf][m + 8][kc + 4]);
            }
#pragma unroll
            for (int nt = 0; nt < 8; nt++) {
                int n = wnb + nt * 8 + gm;
                bf[nt][0] = __float_as_uint(bsl[kc * 136 + n]);
                bf[nt][1] = __float_as_uint(bsl[(kc + 4) * 136 + n]);
            }
#pragma unroll
            for (int mt = 0; mt < 2; mt++)
#pragma unroll
                for (int nt = 0; nt < 8; nt++)
                    mma_tf32(acc[mt][nt], af[mt][0], af[mt][1], af[mt][2], af[mt][3],
                             bf[nt][0], bf[nt][1]);
        }
    }

#pragma unroll
    for (int mt = 0; mt < 2; mt++) {
        int r0 = m0 + wmb + mt * 16 + (lane >> 2);
#pragma unroll
        for (int nt = 0; nt < 8; nt++) {
            int c = wnb + nt * 8 + ((lane & 3) << 1);
            float bb0 = bias[c], bb1 = bias[c + 1];
            float v0 = acc[mt][nt][0] + bb0, v1 = acc[mt][nt][1] + bb1;
            float v2 = acc[mt][nt][2] + bb0, v3 = acc[mt][nt][3] + bb1;
#pragma unroll
            for (int h = 0; h < 2; h++) {
                int r = r0 + h * 8;
                if (r >= M) continue;
                float g0 = h ? v2 : v0, g1 = h ? v3 : v1;
                float o0, o1;
                if (MODE == 0) {
                    o0 = fmaxf(g0, 0.f);
                    o1 = fmaxf(g1, 0.f);
                } else {
                    float2 pv = *(const float2*)(P + (size_t)r * HID + c);
                    float2 qv = *(const float2*)(Q + (size_t)r * HID + c);
                    o0 = g0 * pv.x + (1.f - g0) * qv.x;
                    o1 = g1 * pv.y + (1.f - g1) * qv.y;
                }
                *(float2*)(C + (size_t)r * HID + c) = make_float2(o0, o1);
            }
        }
    }
}

// ---------------------------------------------------------------------------
// gate finalize, dual (img path then txt path): one warp per (set, node)
// ---------------------------------------------------------------------------
__global__ void gate_fin_dual(const float* __restrict__ h2a, const float* __restrict__ h2b,
                              const float* __restrict__ W3a, const float* __restrict__ W3b,
                              const float* __restrict__ b3a, const float* __restrict__ b3b,
                              const float* __restrict__ fa,  const float* __restrict__ fb,
                              const float* __restrict__ emb, const int* __restrict__ nid,
                              float* __restrict__ va, float* __restrict__ vb)
{
    int id = (blockIdx.x * blockDim.x + threadIdx.x) >> 5;
    int lane = threadIdx.x & 31;
    if (id >= 2 * NN) return;
    int set = (id >= NN);
    int w = id - set * NN;
    const float* h2 = set ? h2b : h2a;
    const float* W3 = set ? W3b : W3a;
    const float* b3 = set ? b3b : b3a;
    const float* f  = set ? fb  : fa;
    float* v_out    = set ? vb  : va;

    float4 h4 = *(const float4*)(h2 + (size_t)w * HID + lane * 4);
    float4 w4 = *(const float4*)(W3 + lane * 4);
    float d = h4.x * w4.x + h4.y * w4.y + h4.z * w4.z + h4.w * w4.w;
#pragma unroll
    for (int o = 16; o; o >>= 1) d += __shfl_xor_sync(0xffffffffu, d, o);
    float g = 1.f / (1.f + expf(-(d + b3[0])));
    int e = nid[w];
    float4 fv = *(const float4*)(f + (size_t)w * HID + lane * 4);
    float4 ev = *(const float4*)(emb + (size_t)e * HID + lane * 4);
    float4 o4;
    o4.x = g * fv.x + (1.f - g) * ev.x;
    o4.y = g * fv.y + (1.f - g) * ev.y;
    o4.z = g * fv.z + (1.f - g) * ev.z;
    o4.w = g * fv.w + (1.f - g) * ev.w;
    *(float4*)(v_out + (size_t)w * HID + lane * 4) = o4;
}

// e_src = z . a1, e_dst = z . a2  (one warp per node)
__global__ void attn_e_kernel(const float* __restrict__ z,
                              const float* __restrict__ a,
                              float* __restrict__ es, float* __restrict__ ed)
{
    int w = (blockIdx.x * blockDim.x + threadIdx.x) >> 5;
    int lane = threadIdx.x & 31;
    if (w >= NN) return;
    float4 zv = *(const float4*)(z + (size_t)w * HID + lane * 4);
    float4 a1 = *(const float4*)(a + lane * 4);
    float4 a2 = *(const float4*)(a + HID + lane * 4);
    float d1 = zv.x * a1.x + zv.y * a1.y + zv.z * a1.z + zv.w * a1.w;
    float d2 = zv.x * a2.x + zv.y * a2.y + zv.z * a2.z + zv.w * a2.w;
#pragma unroll
    for (int o = 16; o; o >>= 1) {
        d1 += __shfl_xor_sync(0xffffffffu, d1, o);
        d2 += __shfl_xor_sync(0xffffffffu, d2, o);
    }
    if (lane == 0) { es[w] = d1; ed[w] = d2; }
}

// ---------------------------------------------------------------------------
// Edge phase: CSR by dst, warp-per-dst softmax aggregate (no output atomics)
// ---------------------------------------------------------------------------
__global__ void zero_cnt_kernel()
{
    int i = blockIdx.x * blockDim.x + threadIdx.x;
    if (i < NN) { g_cnt[i] = 0; g_cur[i] = 0; }
}

__global__ void hist_kernel(const int* __restrict__ dst)
{
    int e = blockIdx.x * blockDim.x + threadIdx.x;
    if (e < NE) atomicAdd(&g_cnt[dst[e]], 1);
}

// single-block exclusive scan over g_cnt -> g_start (1024 threads)
__global__ void scan_kernel()
{
    __shared__ int warp_sums[32];
    __shared__ int s_carry;
    int tid = threadIdx.x, lane = tid & 31, wid = tid >> 5;
    if (tid == 0) s_carry = 0;
    __syncthreads();
    for (int base = 0; base < NN; base += 1024) {
        int i = base + tid;
        int v = (i < NN) ? g_cnt[i] : 0;
        int x = v;
#pragma unroll
        for (int o = 1; o < 32; o <<= 1) {
            int y = __shfl_up_sync(0xffffffffu, x, o);
            if (lane >= o) x += y;
        }
        if (lane == 31) warp_sums[wid] = x;
        __syncthreads();
        if (wid == 0) {
            int ws = warp_sums[lane];
#pragma unroll
            for (int o = 1; o < 32; o <<= 1) {
                int y = __shfl_up_sync(0xffffffffu, ws, o);
                if (lane >= o) ws += y;
            }
            warp_sums[lane] = ws;
        }
        __syncthreads();
        int incl = x + (wid ? warp_sums[wid - 1] : 0);
        int carry = s_carry;
        if (i < NN) g_start[i] = carry + incl - v;
        __syncthreads();
        if (tid == 0) s_carry = carry + warp_sums[31];
        __syncthreads();
    }
}

__global__ void scatter_kernel(const int* __restrict__ src, const int* __restrict__ dst)
{
    int e = blockIdx.x * blockDim.x + threadIdx.x;
    if (e >= NE) return;
    int s = src[e], d = dst[e];
    float v = g_esrc[s] + g_edst[d];
    v = (v > 0.f) ? v : 0.01f * v;
    int pos = atomicAdd(&g_cur[d], 1);
    int idx = g_start[d] + pos;
    g_srcs[idx] = s;
    g_es_s[idx] = v;
}

__global__ __launch_bounds__(256)
void aggregate_kernel(float* __restrict__ out)
{
    __shared__ float ws[8][32];
    __shared__ int   ss[8][32];
    int w    = (blockIdx.x * blockDim.x + threadIdx.x) >> 5;
    int lane = threadIdx.x & 31;
    int wib  = (threadIdx.x >> 5);
    if (w >= NN) return;

    int s0  = g_start[w];
    int deg = g_cnt[w];

    float mx = -3.402823466e38f;
    for (int j = lane; j < deg; j += 32) mx = fmaxf(mx, g_es_s[s0 + j]);
#pragma unroll
    for (int o = 16; o; o >>= 1) mx = fmaxf(mx, __shfl_xor_sync(0xffffffffu, mx, o));

    float dsum = 0.f;
    for (int j = lane; j < deg; j += 32) dsum += expf(g_es_s[s0 + j] - mx);
#pragma unroll
    for (int o = 16; o; o >>= 1) dsum += __shfl_xor_sync(0xffffffffu, dsum, o);
    float inv = 1.f / fmaxf(dsum, 1e-20f);

    float4 acc = make_float4(0.f, 0.f, 0.f, 0.f);
    for (int base = 0; base < deg; base += 32) {
        int j = base + lane;
        float wv = 0.f; int sj = 0;
        if (j < deg) {
            wv = expf(g_es_s[s0 + j] - mx) * inv;
            sj = g_srcs[s0 + j];
        }
        ws[wib][lane] = wv;
        ss[wib][lane] = sj;
        __syncwarp();
        int lim = min(32, deg - base);
        for (int jj = 0; jj < lim; jj++) {
            float wj = ws[wib][jj];
            const float4 zv = *(const float4*)(g_z + (size_t)ss[wib][jj] * HID + lane * 4);
            acc.x += wj * zv.x; acc.y += wj * zv.y;
            acc.z += wj * zv.z; acc.w += wj * zv.w;
        }
        __syncwarp();
    }
    *(float4*)(out + (size_t)w * HID + lane * 4) = acc;
}

// ---------------------------------------------------------------------------
// host: tensormap encode via runtime-resolved driver entry point (no -lcuda)
// ---------------------------------------------------------------------------
typedef CUresult (*TMEncodeFn)(CUtensorMap*, CUtensorMapDataType, cuuint32_t, void*,
                               const cuuint64_t*, const cuuint64_t*,
                               const cuuint32_t*, const cuuint32_t*,
                               CUtensorMapInterleave, CUtensorMapSwizzle,
                               CUtensorMapL2promotion, CUtensorMapFloatOOBfill);

static void make_map_a(TMEncodeFn enc, CUtensorMap* m, const void* ptr, int Mrows, int Kcols)
{
    cuuint64_t dims[2]    = {(cuuint64_t)Kcols, (cuuint64_t)Mrows};
    cuuint64_t strides[1] = {(cuuint64_t)Kcols * 4};
    cuuint32_t box[2]     = {16, 128};
    cuuint32_t es[2]      = {1, 1};
    enc(m, CU_TENSOR_MAP_DATA_TYPE_FLOAT32, 2, (void*)ptr, dims, strides, box, es,
        CU_TENSOR_MAP_INTERLEAVE_NONE, CU_TENSOR_MAP_SWIZZLE_64B,
        CU_TENSOR_MAP_L2_PROMOTION_L2_128B, CU_TENSOR_MAP_FLOAT_OOB_FILL_NONE);
}

extern "C" void kernel_launch(void* const* d_in, const int* in_sizes, int n_in,
                              void* d_out, int out_size)
{
    const int*   node_id = (const int*)  d_in[0];
    const float* img_h   = (const float*)d_in[1];
    const float* txt_h   = (const float*)d_in[2];
    const int*   src     = (const int*)  d_in[3];
    const int*   dst     = (const int*)  d_in[4];
    const float* emb     = (const float*)d_in[5];
    const float* W_img   = (const float*)d_in[6];
    const float* img_W1  = (const float*)d_in[7];
    const float* img_b1  = (const float*)d_in[8];
    const float* img_W2  = (const float*)d_in[9];
    const float* img_b2  = (const float*)d_in[10];
    const float* img_W3  = (const float*)d_in[11];
    const float* img_b3  = (const float*)d_in[12];
    const float* W_txt   = (const float*)d_in[13];
    const float* txt_W1  = (const float*)d_in[14];
    const float* txt_b1  = (const float*)d_in[15];
    const float* txt_W2  = (const float*)d_in[16];
    const float* txt_b2  = (const float*)d_in[17];
    const float* txt_W3  = (const float*)d_in[18];
    const float* txt_b3  = (const float*)d_in[19];
    const float* comb_W  = (const float*)d_in[20];
    const float* comb_b  = (const float*)d_in[21];
    const float* fc_W    = (const float*)d_in[22];
    const float* attn_a  = (const float*)d_in[23];
    float* out = (float*)d_out;

    float *imgf, *txtf, *h1a, *h1b, *h2a, *h2b, *imgv, *txtv, *hb, *zb, *es, *ed, *wtf;
    cudaGetSymbolAddress((void**)&imgf, g_img_f);
    cudaGetSymbolAddress((void**)&txtf, g_txt_f);
    cudaGetSymbolAddress((void**)&h1a,  g_h1a);
    cudaGetSymbolAddress((void**)&h1b,  g_h1b);
    cudaGetSymbolAddress((void**)&h2a,  g_h2a);
    cudaGetSymbolAddress((void**)&h2b,  g_h2b);
    cudaGetSymbolAddress((void**)&imgv, g_img_v);
    cudaGetSymbolAddress((void**)&txtv, g_txt_v);
    cudaGetSymbolAddress((void**)&hb,   g_hbuf);
    cudaGetSymbolAddress((void**)&zb,   g_z);
    cudaGetSymbolAddress((void**)&es,   g_esrc);
    cudaGetSymbolAddress((void**)&ed,   g_edst);
    cudaGetSymbolAddress((void**)&wtf,  g_wtf);

    // resolve cuTensorMapEncodeTiled through the runtime (no libcuda link needed)
    void* pfn = nullptr;
    cudaDriverEntryPointQueryResult qr;
#if CUDART_VERSION >= 12050
    cudaGetDriverEntryPointByVersion("cuTensorMapEncodeTiled", &pfn, 12000,
                                     cudaEnableDefault, &qr);
#else
    cudaGetDriverEntryPoint("cuTensorMapEncodeTiled", &pfn, cudaEnableDefault, &qr);
#endif
    TMEncodeFn enc = (TMEncodeFn)pfn;

    CUtensorMap mImg, mTxt, mH1a, mH1b, mHb;
    make_map_a(enc, &mImg, img_h, NN, 2048);
    make_map_a(enc, &mTxt, txt_h, NN, 768);
    make_map_a(enc, &mH1a, h1a,   NN, 128);
    make_map_a(enc, &mH1b, h1b,   NN, 128);
    make_map_a(enc, &mHb,  hb,    NN, 128);

    cudaFuncSetAttribute(gemm_tc_tma<false, false, true >, cudaFuncAttributeMaxDynamicSharedMemorySize, GEMM_SMEM_TMA);
    cudaFuncSetAttribute(gemm_tc_tma<true,  true,  true >, cudaFuncAttributeMaxDynamicSharedMemorySize, GEMM_SMEM_TMA);
    cudaFuncSetAttribute(gemm_tc_tma<false, false, false>, cudaFuncAttributeMaxDynamicSharedMemorySize, GEMM_SMEM_TMA);
    cudaFuncSetAttribute(gemm_tc_cat<0, true >,            cudaFuncAttributeMaxDynamicSharedMemorySize, GEMM_SMEM_CAT);
    cudaFuncSetAttribute(gemm_tc_cat<1, false>,            cudaFuncAttributeMaxDynamicSharedMemorySize, GEMM_SMEM_CAT);

    const int GB = (NN + 127) / 128;                      // 391 tile-rows
    const dim3 GB2(GB, 2);
    const int WARP_BLKS  = (NN * 32 + 255) / 256;
    const int WARP_BLKS2 = (2 * NN * 32 + 255) / 256;

    // 0) pre-round all weight matrices to tf32 into the padded stage layout
    wconv_kernel<<<(STOT + 255) / 256, 256>>>(W_img, W_txt, img_W1, img_W2,
                                              txt_W1, txt_W2, comb_W, fc_W);

    // 1) feature projections, img+txt fused (TMA A; y=0: K=2048, y=1: K=768)
    gemm_tc_tma<false, false, true><<<GB2, 256, GEMM_SMEM_TMA>>>(
        mImg, mTxt, wtf + PWIMG, nullptr, imgf, NN, 2048,
        wtf + PWTXT, nullptr, txtf, 768);

    // 2) gate MLP layer 1, img+txt fused (concat gather GEMM, LDGSTS A)
    gemm_tc_cat<0, true><<<GB2, 256, GEMM_SMEM_CAT>>>(
        emb, imgf, node_id, wtf + PIW1, img_b1, h1a, NN,
        txtf, wtf + PTW1, txt_b1, h1b);

    // 3) gate MLP layer 2, img+txt fused (TMA A)
    gemm_tc_tma<true, true, true><<<GB2, 256, GEMM_SMEM_TMA>>>(
        mH1a, mH1b, wtf + PIW2, img_b2, h2a, NN, 128,
        wtf + PTW2, txt_b2, h2b, 128);

    // 4) gate finalize, both paths
    gate_fin_dual<<<WARP_BLKS2, 256>>>(h2a, h2b, img_W3, txt_W3, img_b3, txt_b3,
                                       imgf, txtf, emb, node_id, imgv, txtv);

    // 5) combine gate + blend
    gemm_tc_cat<1, false><<<GB, 256, GEMM_SMEM_CAT>>>(
        imgv, txtv, nullptr, wtf + PCW, comb_b, hb, NN,
        nullptr, nullptr, nullptr, nullptr);

    // 6) fc projection -> z (TMA A)
    gemm_tc_tma<false, false, false><<<GB, 256, GEMM_SMEM_TMA>>>(
        mHb, mHb, wtf + PFW, nullptr, zb, NN, 128,
        nullptr, nullptr, nullptr, 128);

    // 7) attention scalars
    attn_e_kernel<<<WARP_BLKS, 256>>>(zb, attn_a, es, ed);

    // 8) edge softmax + aggregate via CSR (no output atomics)
    zero_cnt_kernel<<<(NN + 255) / 256, 256>>>();
    hist_kernel<<<(NE + 255) / 256, 256>>>(dst);
    scan_kernel<<<1, 1024>>>();
    scatter_kernel<<<(NE + 255) / 256, 256>>>(src, dst);
    aggregate_kernel<<<(NN * 32 + 255) / 256, 256>>>(out);
}